// round 6
// baseline (speedup 1.0000x reference)
#include <cuda_runtime.h>
#include <math.h>
#include <stdint.h>

typedef unsigned long long u64;

static constexpr int B_  = 4;
static constexpr int L_  = 1024;
static constexpr int D_  = 768;
static constexpr int H_  = 12;
static constexpr int HD_ = 64;
static constexpr int TQ_ = 128;
static constexpr int TK_ = 128;     // pass-1 K-chunk
static constexpr int TK2_ = 64;     // pass-2 K-chunk
static constexpr int NCH_  = L_ / TK_;    // 8
static constexpr int NCH2_ = L_ / TK2_;   // 16

// attn dynamic smem: pass1 Qsd[64][132] u64 + Ks[64][132] f32 = 101376 B (max)
static constexpr int DYN_SMEM_BYTES = 64*132*8 + 64*132*4;   // 101376

// ---------------- packed f32x2 helpers ----------------
__device__ __forceinline__ u64 pack2(float v) {
    u64 r; asm("mov.b64 %0, {%1, %1};" : "=l"(r) : "f"(v)); return r;
}
__device__ __forceinline__ void fma2(u64& c, u64 a, u64 b) {
    asm("fma.rn.f32x2 %0, %1, %2, %0;" : "+l"(c) : "l"(a), "l"(b));
}
__device__ __forceinline__ void add2(u64& c, u64 a) {
    asm("add.rn.f32x2 %0, %0, %1;" : "+l"(c) : "l"(a));
}
__device__ __forceinline__ float2 unp(u64 v) {
    float2 f; asm("mov.b64 {%0, %1}, %2;" : "=f"(f.x), "=f"(f.y) : "l"(v)); return f;
}

// ---------------- device scratch ----------------
__device__ float g_q[(size_t)B_ * L_ * D_];
__device__ float g_k[(size_t)B_ * L_ * D_];
__device__ float g_v[(size_t)B_ * L_ * D_];
__device__ float g_w[(size_t)B_ * L_ * D_];

// ---------------- SGEMM core: C[128,128] tile of A[M,768] @ W[768,768]^T ----
// A dup'd in smem (u64 {a,a}); B natural f32, read as n-pair f32x2.
// Zero MOV packs in the inner loop. Single buffer, reg prefetch.
__device__ __forceinline__ void sgemm_128(const float* __restrict__ A,
                                          const float* __restrict__ W,
                                          const float* __restrict__ bias,
                                          float* __restrict__ C,
                                          int m0, int n0)
{
    __shared__ u64   Asd[8][132];
    __shared__ float Bs [8][132];
    const int tid  = threadIdx.x;
    const int tx   = tid & 15, ty = tid >> 4;
    const int lrow = tid >> 1;
    const int lk4  = (tid & 1) * 4;

    const float* Ap = A + (size_t)(m0 + lrow) * D_ + lk4;
    const float* Wp = W + (size_t)(n0 + lrow) * D_ + lk4;

    u64 acc[8][2][2] = {};   // [m i][n-half g][n-pair]

    float4 av = *(const float4*)Ap;
    float4 wv = *(const float4*)Wp;

    const int NT = D_ / 8;   // 96
    for (int kt = 0; kt < NT; kt++) {
        Asd[lk4+0][lrow] = pack2(av.x); Asd[lk4+1][lrow] = pack2(av.y);
        Asd[lk4+2][lrow] = pack2(av.z); Asd[lk4+3][lrow] = pack2(av.w);
        Bs [lk4+0][lrow] = wv.x;        Bs [lk4+1][lrow] = wv.y;
        Bs [lk4+2][lrow] = wv.z;        Bs [lk4+3][lrow] = wv.w;
        __syncthreads();
        if (kt + 1 < NT) {
            av = *(const float4*)(Ap + (kt + 1) * 8);
            wv = *(const float4*)(Wp + (kt + 1) * 8);
        }
        #pragma unroll
        for (int kk = 0; kk < 8; kk++) {
            ulonglong2 a01 = *(const ulonglong2*)&Asd[kk][ty*8];
            ulonglong2 a23 = *(const ulonglong2*)&Asd[kk][ty*8 + 2];
            ulonglong2 a45 = *(const ulonglong2*)&Asd[kk][ty*8 + 4];
            ulonglong2 a67 = *(const ulonglong2*)&Asd[kk][ty*8 + 6];
            ulonglong2 b0  = *(const ulonglong2*)&Bs[kk][4*tx];
            ulonglong2 b1  = *(const ulonglong2*)&Bs[kk][64 + 4*tx];
            u64 a[8] = {a01.x, a01.y, a23.x, a23.y, a45.x, a45.y, a67.x, a67.y};
            #pragma unroll
            for (int i = 0; i < 8; i++) {
                fma2(acc[i][0][0], a[i], b0.x);
                fma2(acc[i][0][1], a[i], b0.y);
                fma2(acc[i][1][0], a[i], b1.x);
                fma2(acc[i][1][1], a[i], b1.y);
            }
        }
        __syncthreads();
    }

    #pragma unroll
    for (int i = 0; i < 8; i++) {
        const int r = m0 + ty*8 + i;
        #pragma unroll
        for (int g = 0; g < 2; g++) {
            const int c = n0 + g*64 + 4*tx;
            float2 u0 = unp(acc[i][g][0]);
            float2 u1 = unp(acc[i][g][1]);
            float4 o = make_float4(u0.x, u0.y, u1.x, u1.y);
            if (bias) {
                o.x += bias[c+0]; o.y += bias[c+1];
                o.z += bias[c+2]; o.w += bias[c+3];
            }
            *(float4*)&C[(size_t)r * D_ + c] = o;
        }
    }
}

__global__ __launch_bounds__(256, 2)
void sgemm_qkv_kernel(const float* __restrict__ Aq, const float* __restrict__ Ak,
                      const float* __restrict__ Av,
                      const float* __restrict__ Wq, const float* __restrict__ Wk,
                      const float* __restrict__ Wv,
                      float* __restrict__ Cq, float* __restrict__ Ck,
                      float* __restrict__ Cv)
{
    const int sel = blockIdx.x / 6;
    const int n0  = (blockIdx.x % 6) * 128;
    const int m0  = blockIdx.y * 128;
    const float* A = (sel == 0) ? Aq : (sel == 1) ? Ak : Av;
    const float* W = (sel == 0) ? Wq : (sel == 1) ? Wk : Wv;
    float*       C = (sel == 0) ? Cq : (sel == 1) ? Ck : Cv;
    sgemm_128(A, W, nullptr, C, m0, n0);
}

__global__ __launch_bounds__(256, 2)
void sgemm_proj_kernel(const float* __restrict__ A, const float* __restrict__ W,
                       const float* __restrict__ bias, float* __restrict__ C)
{
    sgemm_128(A, W, bias, C, blockIdx.y * 128, blockIdx.x * 128);
}

// ---------------- fused relative-position attention ----------------------
// One block per (b, h, 128-query-row tile). 256 threads, 2 blocks/SM.
// Logits stored pre-scaled by 8*log2(e); exp via exp2f.
__global__ __launch_bounds__(256, 2)
void attn_kernel(const float* __restrict__ gq, const float* __restrict__ gk,
                 const float* __restrict__ gv,
                 const float* __restrict__ relk, const float* __restrict__ relv,
                 float* __restrict__ attn, float* __restrict__ gw)
{
    extern __shared__ float dsm[];
    // pass1 views
    u64*   Qsd = (u64*)dsm;                 // [64 d][132 m]  dup'd
    float* Ks  = dsm + 64*132*2;            // [64 d][132 n]  f32
    // pass2 views (overlap)
    float* Es  = dsm;                       // [64 k][132 m]  f32 (m contiguous)
    u64*   Vsd = (u64*)(dsm + 64*132);      // [64 k][66 d]   dup'd
    u64*   Red = (u64*)dsm;                 // k-split reduce scratch

    __shared__ float sh_relk[7*HD_];
    __shared__ float sh_relv[7*HD_];
    __shared__ float sh_bias[TQ_*7];
    __shared__ float sh_rowmax[TQ_];
    __shared__ float sh_T[TQ_];
    __shared__ float sh_S0[TQ_];
    __shared__ float sh_S6[TQ_];
    __shared__ float sh_pmid[TQ_*5];

    const int q0  = blockIdx.x * TQ_;
    const int h   = blockIdx.y;
    const int b   = blockIdx.z;
    const int tid = threadIdx.x;
    const int tx  = tid & 15, ty = tid >> 4;

    const float CSC = 8.f * 1.44269504088896340736f;   // 8 * log2(e)

    for (int i = tid; i < 7*HD_; i += 256) { sh_relk[i] = relk[i]; sh_relv[i] = relv[i]; }
    for (int i = tid; i < TQ_*5; i += 256) sh_pmid[i] = 0.f;

    const float* qbase = gq + ((size_t)(b*L_ + q0))*D_ + h*HD_;
    const float* kbase = gk + ((size_t)b*L_)*D_ + h*HD_;
    const float* vbase = gv + ((size_t)b*L_)*D_ + h*HD_;
    float* attn_base = attn + (((size_t)(b*H_ + h))*L_ + q0) * L_;

    // ---- Q load, transposed + dup'd: Qsd[d][m] = {q,q} ----
    {
        const int lm = tid >> 1;            // 0..127 (m)
        const int d0 = (tid & 1) * 4;
        #pragma unroll
        for (int r = 0; r < 8; r++) {
            int d = d0 + 8*r;
            float4 v = *(const float4*)(qbase + (size_t)lm*D_ + d);
            Qsd[(d+0)*132 + lm] = pack2(v.x);
            Qsd[(d+1)*132 + lm] = pack2(v.y);
            Qsd[(d+2)*132 + lm] = pack2(v.z);
            Qsd[(d+3)*132 + lm] = pack2(v.w);
        }
    }
    __syncthreads();

    // ---- rel-k bias: bias[m][r] = Q[m] . rel_k[r]  (unscaled) ----
    for (int idx = tid; idx < TQ_*7; idx += 256) {
        int m = idx / 7, rr = idx % 7;
        float s = 0.f;
        #pragma unroll
        for (int d = 0; d < HD_; d++)
            s = fmaf(*(const float*)&Qsd[d*132 + m], sh_relk[rr*HD_ + d], s);
        sh_bias[idx] = s;
    }
    __syncthreads();

    float pmax[2][4];
    #pragma unroll
    for (int mi = 0; mi < 2; mi++)
        #pragma unroll
        for (int i = 0; i < 4; i++) pmax[mi][i] = -1e30f;

    // ================= pass 1: logits (pre-scaled by 8*log2e) =================
    for (int kc = 0; kc < NCH_; kc++) {
        const int k0 = kc * TK_;
        // K loader: transposed f32 into Ks[d][n]
        {
            const int ln  = tid >> 1;
            const int dk0 = (tid & 1) * 4;
            #pragma unroll
            for (int r = 0; r < 8; r++) {
                int d = dk0 + 8*r;
                float4 v = *(const float4*)(kbase + (size_t)(k0 + ln)*D_ + d);
                Ks[(d+0)*132 + ln] = v.x; Ks[(d+1)*132 + ln] = v.y;
                Ks[(d+2)*132 + ln] = v.z; Ks[(d+3)*132 + ln] = v.w;
            }
        }
        __syncthreads();

        u64 acc[2][2][4][2] = {};   // [m-half mi][n-half g][m i][n-pair]
        #pragma unroll 8
        for (int d = 0; d < HD_; d++) {
            ulonglong2 a0l = *(const ulonglong2*)&Qsd[d*132 + ty*4];
            ulonglong2 a0h = *(const ulonglong2*)&Qsd[d*132 + ty*4 + 2];
            ulonglong2 a1l = *(const ulonglong2*)&Qsd[d*132 + 64 + ty*4];
            ulonglong2 a1h = *(const ulonglong2*)&Qsd[d*132 + 64 + ty*4 + 2];
            ulonglong2 b0  = *(const ulonglong2*)&Ks[d*132 + 4*tx];
            ulonglong2 b1  = *(const ulonglong2*)&Ks[d*132 + 64 + 4*tx];
            u64 a[2][4] = {{a0l.x, a0l.y, a0h.x, a0h.y},
                           {a1l.x, a1l.y, a1h.x, a1h.y}};
            #pragma unroll
            for (int mi = 0; mi < 2; mi++)
                #pragma unroll
                for (int i = 0; i < 4; i++) {
                    fma2(acc[mi][0][i][0], a[mi][i], b0.x);
                    fma2(acc[mi][0][i][1], a[mi][i], b0.y);
                    fma2(acc[mi][1][i][0], a[mi][i], b1.x);
                    fma2(acc[mi][1][i][1], a[mi][i], b1.y);
                }
        }

        #pragma unroll
        for (int mi = 0; mi < 2; mi++)
            #pragma unroll
            for (int i = 0; i < 4; i++) {
                const int m  = mi*64 + ty*4 + i;
                const int qg = q0 + m;
                const float* brow = &sh_bias[m*7];
                #pragma unroll
                for (int g = 0; g < 2; g++) {
                    float2 u0 = unp(acc[mi][g][i][0]);
                    float2 u1 = unp(acc[mi][g][i][1]);
                    float vv[4] = {u0.x, u0.y, u1.x, u1.y};
                    float o[4];
                    #pragma unroll
                    for (int c = 0; c < 4; c++) {
                        int kg  = k0 + g*64 + 4*tx + c;
                        int dlt = kg - qg;
                        int rr  = dlt < -3 ? 0 : (dlt > 3 ? 6 : dlt + 3);
                        float s = CSC * (vv[c] + brow[rr]);
                        o[c] = s;
                        pmax[mi][i] = fmaxf(pmax[mi][i], s);
                    }
                    *(float4*)(attn_base + (size_t)m*L_ + k0 + g*64 + 4*tx)
                        = make_float4(o[0], o[1], o[2], o[3]);
                }
            }
        __syncthreads();
    }

    // ---- row-max reduce across the 16 tx lanes ----
    #pragma unroll
    for (int mi = 0; mi < 2; mi++)
        #pragma unroll
        for (int i = 0; i < 4; i++) {
            float v = pmax[mi][i];
            #pragma unroll
            for (int off = 8; off > 0; off >>= 1)
                v = fmaxf(v, __shfl_xor_sync(0xffffffffu, v, off));
            if (tx == 0) sh_rowmax[mi*64 + ty*4 + i] = v;
        }
    __syncthreads();

    // ================= pass 2: exp + sums + PV (TK2=64, k-split-2) ==========
    const int m2  = tid >> 1;        // exp-stage row (0..127)
    const int c0  = (tid & 1) * 4;
    const int qg2 = q0 + m2;
    const float rm2 = sh_rowmax[m2];

    const int g   = tid >> 7;        // k-split group
    const int t2  = tid & 127;
    const int tym = t2 >> 3;         // 16 m-groups of 8
    const int txd = t2 & 7;          // 8 d-groups of 8

    float tsum = 0.f, s0sum = 0.f, s6sum = 0.f;
    u64 acc2[4][8] = {};             // [m-pair p][d j]

    for (int kc = 0; kc < NCH2_; kc++) {
        const int k0 = kc * TK2_;
        // V loader: dup'd into Vsd[k][d]
        {
            const int lnv = tid >> 2;          // 0..63
            const int dv0 = (tid & 3) * 4;
            #pragma unroll
            for (int r = 0; r < 4; r++) {
                int d = dv0 + 16*r;
                float4 v = *(const float4*)(vbase + (size_t)(k0 + lnv)*D_ + d);
                Vsd[lnv*66 + d + 0] = pack2(v.x);
                Vsd[lnv*66 + d + 1] = pack2(v.y);
                Vsd[lnv*66 + d + 2] = pack2(v.z);
                Vsd[lnv*66 + d + 3] = pack2(v.w);
            }
        }
        // exp stage: row m2, cols c0 + 8r (conflict-free f32 STS, m contiguous)
        #pragma unroll
        for (int r = 0; r < 8; r++) {
            int c = c0 + 8*r;
            float4 sv = *(const float4*)(attn_base + (size_t)m2*L_ + k0 + c);
            float svv[4] = {sv.x, sv.y, sv.z, sv.w};
            #pragma unroll
            for (int j = 0; j < 4; j++) {
                float e = exp2f(svv[j] - rm2);
                tsum += e;
                int dlt = k0 + c + j - qg2;
                if (dlt <= -3)      s0sum += e;
                else if (dlt >= 3)  s6sum += e;
                else                sh_pmid[m2*5 + dlt + 2] = e;
                Es[(c+j)*132 + m2] = e;
            }
        }
        __syncthreads();
        // PV: e natural m-pairs from Es, v dup'd from Vsd
        #pragma unroll 8
        for (int kk = 0; kk < 32; kk++) {
            const int k = g*32 + kk;
            ulonglong2 e01 = *(const ulonglong2*)&Es[k*132 + 8*tym];
            ulonglong2 e23 = *(const ulonglong2*)&Es[k*132 + 8*tym + 4];
            ulonglong2 v0  = *(const ulonglong2*)&Vsd[k*66 + 8*txd];
            ulonglong2 v1  = *(const ulonglong2*)&Vsd[k*66 + 8*txd + 2];
            ulonglong2 v2  = *(const ulonglong2*)&Vsd[k*66 + 8*txd + 4];
            ulonglong2 v3  = *(const ulonglong2*)&Vsd[k*66 + 8*txd + 6];
            u64 e[4] = {e01.x, e01.y, e23.x, e23.y};
            u64 v[8] = {v0.x, v0.y, v1.x, v1.y, v2.x, v2.y, v3.x, v3.y};
            #pragma unroll
            for (int p = 0; p < 4; p++)
                #pragma unroll
                for (int j = 0; j < 8; j++)
                    fma2(acc2[p][j], e[p], v[j]);
        }
        __syncthreads();
    }

    // ---- row-sum pair reduce (two threads per row) ----
    tsum  += __shfl_xor_sync(0xffffffffu, tsum,  1);
    s0sum += __shfl_xor_sync(0xffffffffu, s0sum, 1);
    s6sum += __shfl_xor_sync(0xffffffffu, s6sum, 1);
    if ((tid & 1) == 0) { sh_T[m2] = tsum; sh_S0[m2] = s0sum; sh_S6[m2] = s6sum; }
    __syncthreads();

    // ---- k-split pair reduce via smem ----
    if (g == 1) {
        #pragma unroll
        for (int p = 0; p < 4; p++)
            #pragma unroll
            for (int j = 0; j < 8; j++)
                Red[t2*32 + p*8 + j] = acc2[p][j];
    }
    __syncthreads();
    if (g == 0) {
        #pragma unroll
        for (int p = 0; p < 4; p++)
            #pragma unroll
            for (int j = 0; j < 8; j++)
                add2(acc2[p][j], Red[t2*32 + p*8 + j]);

        // ---- w = (w1 + w2) * invT -> scratch [B,L,H,hd] ----
        float* wbase = gw + ((size_t)(b*L_ + q0))*D_ + h*HD_;
        #pragma unroll
        for (int p = 0; p < 4; p++) {
            const int ma = 8*tym + 2*p;      // pair rows ma, ma+1
            float olo[8], ohi[8];
            #pragma unroll
            for (int j = 0; j < 8; j++) {
                float2 u = unp(acc2[p][j]);
                olo[j] = u.x; ohi[j] = u.y;
            }
            #pragma unroll
            for (int half = 0; half < 2; half++) {
                const int m = ma + half;
                float* ov = half ? ohi : olo;
                float T  = sh_T[m];
                float S0 = sh_S0[m];
                float S6 = sh_S6[m];
                float inv = 1.f / T;
                float mids[5];
                #pragma unroll
                for (int rr = 0; rr < 5; rr++) mids[rr] = sh_pmid[m*5 + rr];
                float o[8];
                #pragma unroll
                for (int j = 0; j < 8; j++) {
                    int d = 8*txd + j;
                    float w2 = S0 * sh_relv[d] + S6 * sh_relv[6*HD_ + d];
                    #pragma unroll
                    for (int rr = 0; rr < 5; rr++)
                        w2 = fmaf(mids[rr], sh_relv[(rr+1)*HD_ + d], w2);
                    o[j] = (ov[j] + w2) * inv;
                }
                *(float4*)(wbase + (size_t)m*D_ + 8*txd)     = make_float4(o[0], o[1], o[2], o[3]);
                *(float4*)(wbase + (size_t)m*D_ + 8*txd + 4) = make_float4(o[4], o[5], o[6], o[7]);
            }
        }
    }

    // ================= pass 3: normalized attn out =================
    const float inv3 = 1.f / sh_T[m2];
    #pragma unroll 4
    for (int r = 0; r < 128; r++) {
        int c = c0 + 8*r;
        float* p = attn_base + (size_t)m2*L_ + c;
        float4 a = *(const float4*)p;
        a.x = exp2f(a.x - rm2) * inv3;
        a.y = exp2f(a.y - rm2) * inv3;
        a.z = exp2f(a.z - rm2) * inv3;
        a.w = exp2f(a.w - rm2) * inv3;
        *(float4*)p = a;
    }
}

// ---------------- launch ----------------
extern "C" void kernel_launch(void* const* d_in, const int* in_sizes, int n_in,
                              void* d_out, int out_size)
{
    const float* query  = (const float*)d_in[0];
    const float* key    = (const float*)d_in[1];
    const float* value  = (const float*)d_in[2];
    const float* Wq     = (const float*)d_in[3];
    const float* Wk     = (const float*)d_in[4];
    const float* Wv     = (const float*)d_in[5];
    const float* Wproj  = (const float*)d_in[6];
    const float* b_proj = (const float*)d_in[7];
    const float* relk   = (const float*)d_in[8];
    const float* relv   = (const float*)d_in[9];

    float* out  = (float*)d_out;
    float* attn = out + (size_t)B_ * L_ * D_;   // x first, then attn

    float *gq, *gk, *gv, *gw;
    cudaGetSymbolAddress((void**)&gq, g_q);
    cudaGetSymbolAddress((void**)&gk, g_k);
    cudaGetSymbolAddress((void**)&gv, g_v);
    cudaGetSymbolAddress((void**)&gw, g_w);

    cudaFuncSetAttribute(attn_kernel, cudaFuncAttributeMaxDynamicSharedMemorySize,
                         DYN_SMEM_BYTES);

    sgemm_qkv_kernel<<<dim3(18, 32), 256>>>(query, key, value, Wq, Wk, Wv, gq, gk, gv);

    attn_kernel<<<dim3(L_/TQ_, H_, B_), 256, DYN_SMEM_BYTES>>>(
        gq, gk, gv, relk, relv, attn, gw);

    sgemm_proj_kernel<<<dim3(6, 32), 256>>>(gw, Wproj, b_proj, out);
}

// round 7
// speedup vs baseline: 1.2790x; 1.2790x over previous
#include <cuda_runtime.h>
#include <math.h>
#include <stdint.h>

typedef unsigned long long u64;

static constexpr int B_  = 4;
static constexpr int L_  = 1024;
static constexpr int D_  = 768;
static constexpr int H_  = 12;
static constexpr int HD_ = 64;
static constexpr int TQ_ = 128;
static constexpr int TK_ = 128;
static constexpr int NCH_ = L_ / TK_;   // 8

// fused attn smem: Qs[64][132] + Ks[64][132] + Vs[128][68] + Es[128][132]
static constexpr int ATTN_SMEM_FLOATS = 64*132 + 64*132 + 128*68 + 128*132;  // 42496
static constexpr int ATTN_SMEM_BYTES  = ATTN_SMEM_FLOATS * 4;                // 169984

// ---------------- packed f32x2 helpers ----------------
__device__ __forceinline__ u64 pack2(float v) {
    u64 r; asm("mov.b64 %0, {%1, %1};" : "=l"(r) : "f"(v)); return r;
}
__device__ __forceinline__ u64 pack2xy(float lo, float hi) {
    u64 r; asm("mov.b64 %0, {%1, %2};" : "=l"(r) : "f"(lo), "f"(hi)); return r;
}
__device__ __forceinline__ void fma2(u64& c, u64 a, u64 b) {
    asm("fma.rn.f32x2 %0, %1, %2, %0;" : "+l"(c) : "l"(a), "l"(b));
}
__device__ __forceinline__ void mul2(u64& c, u64 a) {
    asm("mul.rn.f32x2 %0, %0, %1;" : "+l"(c) : "l"(a));
}
__device__ __forceinline__ float2 unp(u64 v) {
    float2 f; asm("mov.b64 {%0, %1}, %2;" : "=f"(f.x), "=f"(f.y) : "l"(v)); return f;
}

// ---------------- device scratch ----------------
__device__ float g_q[(size_t)B_ * L_ * D_];
__device__ float g_k[(size_t)B_ * L_ * D_];
__device__ float g_v[(size_t)B_ * L_ * D_];
__device__ float g_w[(size_t)B_ * L_ * D_];

// ---------------- SGEMM (exact R4 winner): C = A @ W^T (+bias) -----------
__device__ __forceinline__ void sgemm_128(const float* __restrict__ A,
                                          const float* __restrict__ W,
                                          const float* __restrict__ bias,
                                          float* __restrict__ C,
                                          int m0, int n0)
{
    __shared__ float As[8][132];
    __shared__ float Bs[8][132];
    const int tid  = threadIdx.x;
    const int tx   = tid & 15, ty = tid >> 4;
    const int lrow = tid >> 1;
    const int lk4  = (tid & 1) * 4;

    const float* Ap = A + (size_t)(m0 + lrow) * D_ + lk4;
    const float* Wp = W + (size_t)(n0 + lrow) * D_ + lk4;

    u64 acc[2][2][4][2] = {};

    for (int kt = 0; kt < D_; kt += 8) {
        float4 av = *(const float4*)(Ap + kt);
        float4 wv = *(const float4*)(Wp + kt);
        As[lk4+0][lrow] = av.x; As[lk4+1][lrow] = av.y;
        As[lk4+2][lrow] = av.z; As[lk4+3][lrow] = av.w;
        Bs[lk4+0][lrow] = wv.x; Bs[lk4+1][lrow] = wv.y;
        Bs[lk4+2][lrow] = wv.z; Bs[lk4+3][lrow] = wv.w;
        __syncthreads();
        #pragma unroll
        for (int kk = 0; kk < 8; kk++) {
            float4 a0 = *(const float4*)&As[kk][ty*4];
            float4 a1 = *(const float4*)&As[kk][64 + ty*4];
            ulonglong2 b0 = *(const ulonglong2*)&Bs[kk][tx*4];
            ulonglong2 b1 = *(const ulonglong2*)&Bs[kk][64 + tx*4];
            u64 ap[2][4] = {{pack2(a0.x), pack2(a0.y), pack2(a0.z), pack2(a0.w)},
                            {pack2(a1.x), pack2(a1.y), pack2(a1.z), pack2(a1.w)}};
            #pragma unroll
            for (int mi = 0; mi < 2; mi++)
                #pragma unroll
                for (int i = 0; i < 4; i++) {
                    fma2(acc[mi][0][i][0], ap[mi][i], b0.x);
                    fma2(acc[mi][0][i][1], ap[mi][i], b0.y);
                    fma2(acc[mi][1][i][0], ap[mi][i], b1.x);
                    fma2(acc[mi][1][i][1], ap[mi][i], b1.y);
                }
        }
        __syncthreads();
    }

    #pragma unroll
    for (int mi = 0; mi < 2; mi++)
        #pragma unroll
        for (int i = 0; i < 4; i++) {
            int r = m0 + mi*64 + ty*4 + i;
            #pragma unroll
            for (int nj = 0; nj < 2; nj++) {
                int c = n0 + nj*64 + tx*4;
                float2 p0 = unp(acc[mi][nj][i][0]);
                float2 p1 = unp(acc[mi][nj][i][1]);
                float4 o = make_float4(p0.x, p0.y, p1.x, p1.y);
                if (bias) {
                    o.x += bias[c+0]; o.y += bias[c+1];
                    o.z += bias[c+2]; o.w += bias[c+3];
                }
                *(float4*)&C[(size_t)r * D_ + c] = o;
            }
        }
}

__global__ __launch_bounds__(256)
void sgemm_qkv_kernel(const float* __restrict__ Aq, const float* __restrict__ Ak,
                      const float* __restrict__ Av,
                      const float* __restrict__ Wq, const float* __restrict__ Wk,
                      const float* __restrict__ Wv,
                      float* __restrict__ Cq, float* __restrict__ Ck,
                      float* __restrict__ Cv)
{
    const int sel = blockIdx.x / 6;
    const int n0  = (blockIdx.x % 6) * 128;
    const int m0  = blockIdx.y * 128;
    const float* A = (sel == 0) ? Aq : (sel == 1) ? Ak : Av;
    const float* W = (sel == 0) ? Wq : (sel == 1) ? Wk : Wv;
    float*       C = (sel == 0) ? Cq : (sel == 1) ? Ck : Cv;
    sgemm_128(A, W, nullptr, C, m0, n0);
}

__global__ __launch_bounds__(256)
void sgemm_proj_kernel(const float* __restrict__ A, const float* __restrict__ W,
                       const float* __restrict__ bias, float* __restrict__ C)
{
    sgemm_128(A, W, bias, C, blockIdx.y * 128, blockIdx.x * 128);
}

// ---------------- fused flash attention with relative positions ----------
// One block per (b, h, 128-q-rows). 512 threads, 1 block/SM.
// Online softmax; e~ written once; final in-kernel rescale pass.
__global__ __launch_bounds__(512, 1)
void attn_fused_kernel(const float* __restrict__ gq, const float* __restrict__ gk,
                       const float* __restrict__ gv,
                       const float* __restrict__ relk, const float* __restrict__ relv,
                       float* __restrict__ attn, float* __restrict__ gw)
{
    extern __shared__ float dsm[];
    float* Qs = dsm;                        // [64 d][132 m]
    float* Ks = Qs + 64*132;                // [64 d][132 n]
    float* Vs = Ks + 64*132;                // [128 k][68 d]
    float* Es = Vs + 128*68;                // [128 k][132 m]

    __shared__ float sh_relk[7*HD_];
    __shared__ float sh_relv[7*HD_];
    __shared__ float sh_bias[TQ_*7];
    __shared__ float sh_red[TQ_*33];
    __shared__ float sh_mrow[TQ_];
    __shared__ float sh_f[TQ_];
    __shared__ float sh_S0[TQ_];
    __shared__ float sh_S6[TQ_];
    __shared__ float sh_iT[TQ_];
    __shared__ float sh_pmid[TQ_*5];
    __shared__ float sh_mhist[NCH_*TQ_];

    const int q0  = blockIdx.x * TQ_;
    const int h   = blockIdx.y;
    const int b   = blockIdx.z;
    const int tid = threadIdx.x;
    const int tx  = tid & 15;        // S: m-group (m = 4*tx + i + 64*gm)
    const int tyy = tid >> 4;        // S: n-group (n = 4*tyy + c), 0..31
    const int mgP = tid & 31;        // PV: m = 4*mgP
    const int dgP = tid >> 5;        // PV: d = 4*dgP

    const float CSC = 8.f * 1.44269504088896340736f;   // 8 * log2(e)

    for (int i = tid; i < 7*HD_; i += 512) { sh_relk[i] = relk[i]; sh_relv[i] = relv[i]; }
    for (int i = tid; i < TQ_*5; i += 512) sh_pmid[i] = 0.f;
    if (tid < TQ_) sh_mrow[tid] = -1e30f;

    const float* qbase = gq + ((size_t)(b*L_ + q0))*D_ + h*HD_;
    const float* kbase = gk + ((size_t)b*L_)*D_ + h*HD_;
    const float* vbase = gv + ((size_t)b*L_)*D_ + h*HD_;
    float* attn_base = attn + (((size_t)(b*H_ + h))*L_ + q0) * L_;

    // ---- Q load, transposed: Qs[d][m] ----
    {
        const int lm = tid >> 2;          // 0..127
        const int d0 = (tid & 3) * 4;
        #pragma unroll
        for (int r = 0; r < 4; r++) {
            int d = d0 + 16*r;
            float4 v = *(const float4*)(qbase + (size_t)lm*D_ + d);
            Qs[(d+0)*132 + lm] = v.x;
            Qs[(d+1)*132 + lm] = v.y;
            Qs[(d+2)*132 + lm] = v.z;
            Qs[(d+3)*132 + lm] = v.w;
        }
    }
    __syncthreads();

    // ---- rel-k bias: bias[m][r] = Q[m] . rel_k[r] (unscaled) ----
    for (int idx = tid; idx < TQ_*7; idx += 512) {
        int m = idx / 7, rr = idx % 7;
        float s = 0.f;
        #pragma unroll
        for (int d = 0; d < HD_; d++)
            s = fmaf(Qs[d*132 + m], sh_relk[rr*HD_ + d], s);
        sh_bias[idx] = s;
    }
    __syncthreads();

    float s0r[8] = {0,0,0,0,0,0,0,0};
    float s6r[8] = {0,0,0,0,0,0,0,0};
    u64 pv[2][4] = {};               // [m-pair][d c]

    for (int kc = 0; kc < NCH_; kc++) {
        const int k0 = kc * TK_;
        // ---- K loader (transposed) ----
        {
            const int ln = tid >> 2;
            const int d0 = (tid & 3) * 4;
            #pragma unroll
            for (int r = 0; r < 4; r++) {
                int d = d0 + 16*r;
                float4 v = *(const float4*)(kbase + (size_t)(k0 + ln)*D_ + d);
                Ks[(d+0)*132 + ln] = v.x;
                Ks[(d+1)*132 + ln] = v.y;
                Ks[(d+2)*132 + ln] = v.z;
                Ks[(d+3)*132 + ln] = v.w;
            }
        }
        // ---- V loader (row-major) ----
        {
            const int ln = tid >> 2;
            const int d0 = (tid & 3) * 16;
            #pragma unroll
            for (int t = 0; t < 4; t++) {
                float4 v = *(const float4*)(vbase + (size_t)(k0 + ln)*D_ + d0 + 4*t);
                *(float4*)&Vs[ln*68 + d0 + 4*t] = v;
            }
        }
        __syncthreads();

        // ---- S compute: m-pair accumulators, Q natural pairs, K dup'd ----
        u64 sa[2][4][2] = {};   // [gm][n c][m-pair]
        #pragma unroll 8
        for (int d = 0; d < HD_; d++) {
            ulonglong2 qp0 = *(const ulonglong2*)&Qs[d*132 + 4*tx];
            ulonglong2 qp1 = *(const ulonglong2*)&Qs[d*132 + 64 + 4*tx];
            float4 kv = *(const float4*)&Ks[d*132 + 4*tyy];
            u64 kd[4] = {pack2(kv.x), pack2(kv.y), pack2(kv.z), pack2(kv.w)};
            #pragma unroll
            for (int c = 0; c < 4; c++) {
                fma2(sa[0][c][0], qp0.x, kd[c]);
                fma2(sa[0][c][1], qp0.y, kd[c]);
                fma2(sa[1][c][0], qp1.x, kd[c]);
                fma2(sa[1][c][1], qp1.y, kd[c]);
            }
        }

        // ---- phase A: chunk rowmax (with bias+scale), stage, reduce ----
        #pragma unroll
        for (int gm = 0; gm < 2; gm++) {
            float cmax[4] = {-1e30f, -1e30f, -1e30f, -1e30f};
            #pragma unroll
            for (int c = 0; c < 4; c++) {
                float2 u0 = unp(sa[gm][c][0]);
                float2 u1 = unp(sa[gm][c][1]);
                float vv[4] = {u0.x, u0.y, u1.x, u1.y};
                #pragma unroll
                for (int i = 0; i < 4; i++) {
                    const int m  = gm*64 + 4*tx + i;
                    const int dlt = (k0 + 4*tyy + c) - (q0 + m);
                    const int rr  = dlt < -3 ? 0 : (dlt > 3 ? 6 : dlt + 3);
                    float s = CSC * (vv[i] + sh_bias[m*7 + rr]);
                    cmax[i] = fmaxf(cmax[i], s);
                }
            }
            #pragma unroll
            for (int i = 0; i < 4; i++)
                sh_red[(gm*64 + 4*tx + i)*33 + tyy] = cmax[i];
        }
        __syncthreads();
        {
            const int row = tid >> 2, seg = tid & 3;
            float mx = -1e30f;
            #pragma unroll
            for (int j = 0; j < 8; j++)
                mx = fmaxf(mx, sh_red[row*33 + seg*8 + j]);
            mx = fmaxf(mx, __shfl_xor_sync(0xffffffffu, mx, 1));
            mx = fmaxf(mx, __shfl_xor_sync(0xffffffffu, mx, 2));
            if (seg == 0) {
                float mold = sh_mrow[row];
                float mnew = fmaxf(mold, mx);
                float f = exp2f(mold - mnew);
                sh_mrow[row] = mnew;
                sh_f[row] = f;
                sh_mhist[kc*TQ_ + row] = mnew;
                #pragma unroll
                for (int rr = 0; rr < 5; rr++) sh_pmid[row*5 + rr] *= f;
            }
        }
        __syncthreads();

        // ---- phase B: rescale accumulators, compute e~, store ----
        {
            // PV acc rescale (rows 4*mgP .. +3)
            float f0 = sh_f[4*mgP + 0], f1 = sh_f[4*mgP + 1];
            float f2 = sh_f[4*mgP + 2], f3 = sh_f[4*mgP + 3];
            u64 fp0 = pack2xy(f0, f1), fp1 = pack2xy(f2, f3);
            #pragma unroll
            for (int c = 0; c < 4; c++) { mul2(pv[0][c], fp0); mul2(pv[1][c], fp1); }
        }
        #pragma unroll
        for (int gm = 0; gm < 2; gm++) {
            float e[4][4];   // [m i][n c]
            #pragma unroll
            for (int c = 0; c < 4; c++) {
                float2 u0 = unp(sa[gm][c][0]);
                float2 u1 = unp(sa[gm][c][1]);
                e[0][c] = u0.x; e[1][c] = u0.y; e[2][c] = u1.x; e[3][c] = u1.y;
            }
            #pragma unroll
            for (int i = 0; i < 4; i++) {
                const int m  = gm*64 + 4*tx + i;
                const int qg = q0 + m;
                const float mnew = sh_mrow[m];
                const float f    = sh_f[m];
                float a0 = s0r[gm*4+i] * f;
                float a6 = s6r[gm*4+i] * f;
                #pragma unroll
                for (int c = 0; c < 4; c++) {
                    const int kg  = k0 + 4*tyy + c;
                    const int dlt = kg - qg;
                    const int rr  = dlt < -3 ? 0 : (dlt > 3 ? 6 : dlt + 3);
                    float s  = CSC * (e[i][c] + sh_bias[m*7 + rr]);
                    float ee = exp2f(s - mnew);
                    e[i][c] = ee;
                    if (dlt <= -3)      a0 += ee;
                    else if (dlt >= 3)  a6 += ee;
                    else                sh_pmid[m*5 + dlt + 2] = ee;
                }
                s0r[gm*4+i] = a0;
                s6r[gm*4+i] = a6;
                *(float4*)(attn_base + (size_t)m*L_ + k0 + 4*tyy)
                    = make_float4(e[i][0], e[i][1], e[i][2], e[i][3]);
            }
            // Es stores: float4 along m, k-major
            #pragma unroll
            for (int c = 0; c < 4; c++)
                *(float4*)&Es[(4*tyy + c)*132 + gm*64 + 4*tx]
                    = make_float4(e[0][c], e[1][c], e[2][c], e[3][c]);
        }
        __syncthreads();

        // ---- PV accumulate: e natural m-pairs, v broadcast-dup'd ----
        #pragma unroll 4
        for (int k = 0; k < TK_; k++) {
            ulonglong2 ee = *(const ulonglong2*)&Es[k*132 + 4*mgP];
            float4 vv = *(const float4*)&Vs[k*68 + 4*dgP];
            u64 vd[4] = {pack2(vv.x), pack2(vv.y), pack2(vv.z), pack2(vv.w)};
            #pragma unroll
            for (int c = 0; c < 4; c++) {
                fma2(pv[0][c], ee.x, vd[c]);
                fma2(pv[1][c], ee.y, vd[c]);
            }
        }
        __syncthreads();
    }

    // ---- final bucket reduces: s0, s6 ----
    #pragma unroll
    for (int gm = 0; gm < 2; gm++)
        #pragma unroll
        for (int i = 0; i < 4; i++)
            sh_red[(gm*64 + 4*tx + i)*33 + tyy] = s0r[gm*4+i];
    __syncthreads();
    {
        const int row = tid >> 2, seg = tid & 3;
        float sm = 0.f;
        #pragma unroll
        for (int j = 0; j < 8; j++) sm += sh_red[row*33 + seg*8 + j];
        sm += __shfl_xor_sync(0xffffffffu, sm, 1);
        sm += __shfl_xor_sync(0xffffffffu, sm, 2);
        if (seg == 0) sh_S0[row] = sm;
    }
    __syncthreads();
    #pragma unroll
    for (int gm = 0; gm < 2; gm++)
        #pragma unroll
        for (int i = 0; i < 4; i++)
            sh_red[(gm*64 + 4*tx + i)*33 + tyy] = s6r[gm*4+i];
    __syncthreads();
    {
        const int row = tid >> 2, seg = tid & 3;
        float sm = 0.f;
        #pragma unroll
        for (int j = 0; j < 8; j++) sm += sh_red[row*33 + seg*8 + j];
        sm += __shfl_xor_sync(0xffffffffu, sm, 1);
        sm += __shfl_xor_sync(0xffffffffu, sm, 2);
        if (seg == 0) sh_S6[row] = sm;
    }
    __syncthreads();
    if (tid < TQ_) {
        float t = sh_S0[tid] + sh_S6[tid];
        #pragma unroll
        for (int rr = 0; rr < 5; rr++) t += sh_pmid[tid*5 + rr];
        sh_iT[tid] = 1.f / t;
    }
    __syncthreads();

    // ---- w = (PV + w2) * invT -> scratch [B,L,H,hd] ----
    {
        float* wbase = gw + ((size_t)(b*L_ + q0))*D_ + h*HD_;
        float rowv[4][4];   // [m i][d c]
        #pragma unroll
        for (int c = 0; c < 4; c++) {
            float2 u0 = unp(pv[0][c]);
            float2 u1 = unp(pv[1][c]);
            rowv[0][c] = u0.x; rowv[1][c] = u0.y; rowv[2][c] = u1.x; rowv[3][c] = u1.y;
        }
        #pragma unroll
        for (int i = 0; i < 4; i++) {
            const int m = 4*mgP + i;
            float S0 = sh_S0[m], S6 = sh_S6[m], iT = sh_iT[m];
            float mids[5];
            #pragma unroll
            for (int rr = 0; rr < 5; rr++) mids[rr] = sh_pmid[m*5 + rr];
            float o[4];
            #pragma unroll
            for (int c = 0; c < 4; c++) {
                int d = 4*dgP + c;
                float w2 = S0 * sh_relv[d] + S6 * sh_relv[6*HD_ + d];
                #pragma unroll
                for (int rr = 0; rr < 5; rr++)
                    w2 = fmaf(mids[rr], sh_relv[(rr+1)*HD_ + d], w2);
                o[c] = (rowv[i][c] + w2) * iT;
            }
            *(float4*)(wbase + (size_t)m*D_ + 4*dgP) = make_float4(o[0], o[1], o[2], o[3]);
        }
    }

    // ---- final rescale pass: attn = e~ * exp2(m_kc - m_fin) * invT ----
    {
        const int row = tid >> 2, seg = tid & 3;
        const float mfin = sh_mrow[row];
        const float iT   = sh_iT[row];
        float fac[NCH_];
        #pragma unroll
        for (int kc = 0; kc < NCH_; kc++)
            fac[kc] = exp2f(sh_mhist[kc*TQ_ + row] - mfin) * iT;
        float* rbase = attn_base + (size_t)row*L_;
        #pragma unroll 4
        for (int t = 0; t < 64; t++) {
            int col = seg*4 + 16*t;
            float fc = fac[col >> 7];
            float4 a = *(const float4*)(rbase + col);
            a.x *= fc; a.y *= fc; a.z *= fc; a.w *= fc;
            *(float4*)(rbase + col) = a;
        }
    }
}

// ---------------- launch ----------------
extern "C" void kernel_launch(void* const* d_in, const int* in_sizes, int n_in,
                              void* d_out, int out_size)
{
    const float* query  = (const float*)d_in[0];
    const float* key    = (const float*)d_in[1];
    const float* value  = (const float*)d_in[2];
    const float* Wq     = (const float*)d_in[3];
    const float* Wk     = (const float*)d_in[4];
    const float* Wv     = (const float*)d_in[5];
    const float* Wproj  = (const float*)d_in[6];
    const float* b_proj = (const float*)d_in[7];
    const float* relk   = (const float*)d_in[8];
    const float* relv   = (const float*)d_in[9];

    float* out  = (float*)d_out;
    float* attn = out + (size_t)B_ * L_ * D_;   // x first, then attn

    float *gq, *gk, *gv, *gw;
    cudaGetSymbolAddress((void**)&gq, g_q);
    cudaGetSymbolAddress((void**)&gk, g_k);
    cudaGetSymbolAddress((void**)&gv, g_v);
    cudaGetSymbolAddress((void**)&gw, g_w);

    cudaFuncSetAttribute(attn_fused_kernel,
                         cudaFuncAttributeMaxDynamicSharedMemorySize,
                         ATTN_SMEM_BYTES);

    sgemm_qkv_kernel<<<dim3(18, 32), 256>>>(query, key, value, Wq, Wk, Wv, gq, gk, gv);

    attn_fused_kernel<<<dim3(L_/TQ_, H_, B_), 512, ATTN_SMEM_BYTES>>>(
        gq, gk, gv, relk, relv, attn, gw);

    sgemm_proj_kernel<<<dim3(6, 32), 256>>>(gw, Wproj, b_proj, out);
}

// round 11
// speedup vs baseline: 1.3985x; 1.0934x over previous
#include <cuda_runtime.h>
#include <math.h>
#include <stdint.h>

typedef unsigned long long u64;

static constexpr int B_  = 4;
static constexpr int L_  = 1024;
static constexpr int D_  = 768;
static constexpr int H_  = 12;
static constexpr int HD_ = 64;
static constexpr int TQ_ = 128;
static constexpr int TK_ = 128;
static constexpr int NCH_ = L_ / TK_;   // 8

// attn dynamic smem (champion R4 config)
static constexpr int DYN_SMEM_BYTES = (128*132 + 128*68) * 4;   // 100352

// mma GEMM config
static constexpr int KT  = 16;          // k-tile
static constexpr int NKT = D_ / KT;     // 48
static constexpr int PAD = 20;          // floats per smem row (16 used)

// ---------------- packed f32x2 helpers (attn) ----------------
__device__ __forceinline__ u64 pack2(float v) {
    u64 r; asm("mov.b64 %0, {%1, %1};" : "=l"(r) : "f"(v)); return r;
}
__device__ __forceinline__ void fma2(u64& c, u64 a, u64 b) {
    asm("fma.rn.f32x2 %0, %1, %2, %0;" : "+l"(c) : "l"(a), "l"(b));
}
__device__ __forceinline__ void add2(u64& c, u64 a) {
    asm("add.rn.f32x2 %0, %0, %1;" : "+l"(c) : "l"(a));
}
__device__ __forceinline__ float2 unp(u64 v) {
    float2 f; asm("mov.b64 {%0, %1}, %2;" : "=f"(f.x), "=f"(f.y) : "l"(v)); return f;
}

// ---------------- mma.sync helpers ----------------
__device__ __forceinline__ uint32_t smem_u32(const void* p) {
    uint32_t a;
    asm("{ .reg .u64 t; cvta.to.shared.u64 t, %1; cvt.u32.u64 %0, t; }"
        : "=r"(a) : "l"(p));
    return a;
}
__device__ __forceinline__ float tf32_rna(float x) {
    uint32_t r; asm("cvt.rna.tf32.f32 %0, %1;" : "=r"(r) : "f"(x));
    return __uint_as_float(r);
}
__device__ __forceinline__ void ldsm4(uint32_t r[4], uint32_t a) {
    asm volatile("ldmatrix.sync.aligned.m8n8.x4.shared.b16 {%0,%1,%2,%3}, [%4];"
        : "=r"(r[0]), "=r"(r[1]), "=r"(r[2]), "=r"(r[3]) : "r"(a));
}
__device__ __forceinline__ void ldsm2(uint32_t r[2], uint32_t a) {
    asm volatile("ldmatrix.sync.aligned.m8n8.x2.shared.b16 {%0,%1}, [%2];"
        : "=r"(r[0]), "=r"(r[1]) : "r"(a));
}
__device__ __forceinline__ void mma8(float c[4], const uint32_t a[4],
                                     const uint32_t b[2]) {
    asm volatile(
        "mma.sync.aligned.m16n8k8.row.col.f32.tf32.tf32.f32 "
        "{%0,%1,%2,%3}, {%4,%5,%6,%7}, {%8,%9}, {%0,%1,%2,%3};"
        : "+f"(c[0]), "+f"(c[1]), "+f"(c[2]), "+f"(c[3])
        : "r"(a[0]), "r"(a[1]), "r"(a[2]), "r"(a[3]), "r"(b[0]), "r"(b[1]));
}

// ---------------- device scratch ----------------
__device__ float g_q[(size_t)B_ * L_ * D_];
__device__ float g_k[(size_t)B_ * L_ * D_];
__device__ float g_v[(size_t)B_ * L_ * D_];
__device__ float g_w[(size_t)B_ * L_ * D_];

// ---------------- split-tf32 mma.sync GEMM: C[128,64] tile of A@W^T ------
__device__ __forceinline__ void mma_gemm_tile(const float* __restrict__ A,
                                              const float* __restrict__ W,
                                              const float* __restrict__ bias,
                                              float* __restrict__ C,
                                              int m0, int n0)
{
    __shared__ float Ah[128*PAD], Al[128*PAD], Bh[64*PAD], Bl[64*PAD];

    const int tid  = threadIdx.x;
    const int lane = tid & 31, wid = tid >> 5;
    const int wy = wid & 3, wx = wid >> 2;      // 4m x 2n warp grid
    const int gid = lane >> 2, tig = lane & 3;

    // loader indices
    const int rowA = tid >> 1, khA = (tid & 1) * 8;
    const int rowB = tid >> 2, kqB = (tid & 3) * 4;
    const float* Ap = A + (size_t)(m0 + rowA) * D_ + khA;
    const float* Wp = W + (size_t)(n0 + rowB) * D_ + kqB;

    // ldmatrix base addresses (per-thread row pointers)
    uint32_t aAh[2], aAl[2], aBh, aBl;
    {
        int r  = 32*wy + (lane & 7) + 8*((lane >> 3) & 1);
        int kc = 4 * (lane >> 4);
        aAh[0] = smem_u32(&Ah[(r     )*PAD + kc]);
        aAh[1] = smem_u32(&Ah[(r + 16)*PAD + kc]);
        aAl[0] = smem_u32(&Al[(r     )*PAD + kc]);
        aAl[1] = smem_u32(&Al[(r + 16)*PAD + kc]);
        int rB  = 32*wx + (lane & 7);
        int kcB = 4 * ((lane >> 3) & 1);
        aBh = smem_u32(&Bh[rB*PAD + kcB]);
        aBl = smem_u32(&Bl[rB*PAD + kcB]);
    }

    float c[2][4][4] = {};

    float4 va0 = *(const float4*)(Ap);
    float4 va1 = *(const float4*)(Ap + 4);
    float4 vb  = *(const float4*)(Wp);

    for (int kt = 0; kt < NKT; kt++) {
        // split hi/lo and stage
        {
            float4 h0, l0, h1, l1, hb, lb;
            h0.x = tf32_rna(va0.x); l0.x = va0.x - h0.x;
            h0.y = tf32_rna(va0.y); l0.y = va0.y - h0.y;
            h0.z = tf32_rna(va0.z); l0.z = va0.z - h0.z;
            h0.w = tf32_rna(va0.w); l0.w = va0.w - h0.w;
            h1.x = tf32_rna(va1.x); l1.x = va1.x - h1.x;
            h1.y = tf32_rna(va1.y); l1.y = va1.y - h1.y;
            h1.z = tf32_rna(va1.z); l1.z = va1.z - h1.z;
            h1.w = tf32_rna(va1.w); l1.w = va1.w - h1.w;
            hb.x = tf32_rna(vb.x);  lb.x = vb.x - hb.x;
            hb.y = tf32_rna(vb.y);  lb.y = vb.y - hb.y;
            hb.z = tf32_rna(vb.z);  lb.z = vb.z - hb.z;
            hb.w = tf32_rna(vb.w);  lb.w = vb.w - hb.w;
            *(float4*)&Ah[rowA*PAD + khA]     = h0;
            *(float4*)&Ah[rowA*PAD + khA + 4] = h1;
            *(float4*)&Al[rowA*PAD + khA]     = l0;
            *(float4*)&Al[rowA*PAD + khA + 4] = l1;
            *(float4*)&Bh[rowB*PAD + kqB] = hb;
            *(float4*)&Bl[rowB*PAD + kqB] = lb;
        }
        __syncthreads();
        if (kt + 1 < NKT) {
            va0 = *(const float4*)(Ap + (kt+1)*KT);
            va1 = *(const float4*)(Ap + (kt+1)*KT + 4);
            vb  = *(const float4*)(Wp + (kt+1)*KT);
        }
        #pragma unroll
        for (int k8 = 0; k8 < 2; k8++) {
            const uint32_t ko = (uint32_t)(k8 * 8 * 4);   // +8 floats
            uint32_t ah[2][4], al[2][4], bh[4][2], bl[4][2];
            ldsm4(ah[0], aAh[0] + ko);
            ldsm4(ah[1], aAh[1] + ko);
            ldsm4(al[0], aAl[0] + ko);
            ldsm4(al[1], aAl[1] + ko);
            #pragma unroll
            for (int nj = 0; nj < 4; nj++) {
                ldsm2(bh[nj], aBh + (uint32_t)(nj*8*PAD*4) + ko);
                ldsm2(bl[nj], aBl + (uint32_t)(nj*8*PAD*4) + ko);
            }
            #pragma unroll
            for (int mi = 0; mi < 2; mi++)
                #pragma unroll
                for (int nj = 0; nj < 4; nj++) {
                    mma8(c[mi][nj], ah[mi], bh[nj]);
                    mma8(c[mi][nj], ah[mi], bl[nj]);
                    mma8(c[mi][nj], al[mi], bh[nj]);
                }
        }
        __syncthreads();
    }

    // epilogue: fragment-direct float2 stores
    #pragma unroll
    for (int mi = 0; mi < 2; mi++) {
        const int r0 = m0 + 32*wy + 16*mi + gid;
        #pragma unroll
        for (int nj = 0; nj < 4; nj++) {
            const int cc = n0 + 32*wx + 8*nj + 2*tig;
            float2 v0 = make_float2(c[mi][nj][0], c[mi][nj][1]);
            float2 v1 = make_float2(c[mi][nj][2], c[mi][nj][3]);
            if (bias) {
                float bx = bias[cc], by = bias[cc+1];
                v0.x += bx; v0.y += by;
                v1.x += bx; v1.y += by;
            }
            *(float2*)&C[(size_t)r0 * D_ + cc]       = v0;
            *(float2*)&C[(size_t)(r0 + 8) * D_ + cc] = v1;
        }
    }
}

__global__ __launch_bounds__(256)
void mma_qkv_kernel(const float* __restrict__ Aq, const float* __restrict__ Ak,
                    const float* __restrict__ Av,
                    const float* __restrict__ Wq, const float* __restrict__ Wk,
                    const float* __restrict__ Wv,
                    float* __restrict__ Cq, float* __restrict__ Ck,
                    float* __restrict__ Cv)
{
    const int sel = blockIdx.x / 12;
    const int n0  = (blockIdx.x % 12) * 64;
    const int m0  = blockIdx.y * 128;
    const float* A = (sel == 0) ? Aq : (sel == 1) ? Ak : Av;
    const float* W = (sel == 0) ? Wq : (sel == 1) ? Wk : Wv;
    float*       C = (sel == 0) ? Cq : (sel == 1) ? Ck : Cv;
    mma_gemm_tile(A, W, nullptr, C, m0, n0);
}

__global__ __launch_bounds__(256)
void mma_proj_kernel(const float* __restrict__ A, const float* __restrict__ W,
                     const float* __restrict__ bias, float* __restrict__ C)
{
    mma_gemm_tile(A, W, bias, C, blockIdx.y * 128, blockIdx.x * 64);
}

// ---------------- champion attn kernel (R4 bench, unchanged) -------------
__global__ __launch_bounds__(256, 2)
void attn_kernel(const float* __restrict__ gq, const float* __restrict__ gk,
                 const float* __restrict__ gv,
                 const float* __restrict__ relk, const float* __restrict__ relv,
                 float* __restrict__ attn, float* __restrict__ gw)
{
    extern __shared__ float dsm[];
    float* Qs = dsm;              // pass1: [64][132]  d-major
    float* Ks = dsm + 64*132;     // pass1: [64][132]  d-major
    float* Es = dsm;              // pass2: [128][132] k-major (transposed e)
    float* Vs = dsm + 128*132;    // pass2: [128][68]  row-major

    __shared__ float sh_relk[7*HD_];
    __shared__ float sh_relv[7*HD_];
    __shared__ float sh_bias[TQ_*7];
    __shared__ float sh_rowmax[TQ_];
    __shared__ float sh_T[TQ_];
    __shared__ float sh_S0[TQ_];
    __shared__ float sh_S6[TQ_];
    __shared__ float sh_pmid[TQ_*5];

    const int q0  = blockIdx.x * TQ_;
    const int h   = blockIdx.y;
    const int b   = blockIdx.z;
    const int tid = threadIdx.x;
    const int tx  = tid & 15, ty = tid >> 4;
    const int lrow = tid >> 1;          // 0..127
    const int lk4  = (tid & 1) * 4;

    for (int i = tid; i < 7*HD_; i += 256) { sh_relk[i] = relk[i]; sh_relv[i] = relv[i]; }
    for (int i = tid; i < TQ_*5; i += 256) sh_pmid[i] = 0.f;

    const float* qbase = gq + ((size_t)(b*L_ + q0))*D_ + h*HD_;
    const float* kbase = gk + ((size_t)b*L_)*D_ + h*HD_;
    const float* vbase = gv + ((size_t)b*L_)*D_ + h*HD_;
    float* attn_base = attn + (((size_t)(b*H_ + h))*L_ + q0) * L_;

    // ---- Q tile transposed: Qs[d][m], 2-way-conflict STS mapping ----
    #pragma unroll
    for (int r = 0; r < 8; r++) {
        int d = lk4 + r*8;
        float4 v = *(const float4*)(qbase + (size_t)lrow*D_ + d);
        Qs[(d+0)*132 + lrow] = v.x; Qs[(d+1)*132 + lrow] = v.y;
        Qs[(d+2)*132 + lrow] = v.z; Qs[(d+3)*132 + lrow] = v.w;
    }
    __syncthreads();

    // ---- rel-k bias: bias[m][r] = Q[m] . rel_k[r] ----
    for (int idx = tid; idx < TQ_*7; idx += 256) {
        int m = idx / 7, r = idx % 7;
        float s = 0.f;
        #pragma unroll
        for (int d = 0; d < HD_; d++) s = fmaf(Qs[d*132 + m], sh_relk[r*HD_ + d], s);
        sh_bias[idx] = s;
    }

    float pmax[2][4];
    #pragma unroll
    for (int mi = 0; mi < 2; mi++)
        #pragma unroll
        for (int i = 0; i < 4; i++) pmax[mi][i] = -1e30f;

    // ================= pass 1: logits =================
    for (int kc = 0; kc < NCH_; kc++) {
        const int k0 = kc * TK_;
        #pragma unroll
        for (int r = 0; r < 8; r++) {
            int d = lk4 + r*8;
            float4 v = *(const float4*)(kbase + (size_t)(k0 + lrow)*D_ + d);
            Ks[(d+0)*132 + lrow] = v.x; Ks[(d+1)*132 + lrow] = v.y;
            Ks[(d+2)*132 + lrow] = v.z; Ks[(d+3)*132 + lrow] = v.w;
        }
        __syncthreads();

        u64 acc[2][2][4][2] = {};
        #pragma unroll 8
        for (int d = 0; d < HD_; d++) {
            float4 a0 = *(const float4*)&Qs[d*132 + ty*4];
            float4 a1 = *(const float4*)&Qs[d*132 + 64 + ty*4];
            ulonglong2 b0 = *(const ulonglong2*)&Ks[d*132 + tx*4];
            ulonglong2 b1 = *(const ulonglong2*)&Ks[d*132 + 64 + tx*4];
            u64 ap[2][4] = {{pack2(a0.x), pack2(a0.y), pack2(a0.z), pack2(a0.w)},
                            {pack2(a1.x), pack2(a1.y), pack2(a1.z), pack2(a1.w)}};
            #pragma unroll
            for (int mi = 0; mi < 2; mi++)
                #pragma unroll
                for (int i = 0; i < 4; i++) {
                    fma2(acc[mi][0][i][0], ap[mi][i], b0.x);
                    fma2(acc[mi][0][i][1], ap[mi][i], b0.y);
                    fma2(acc[mi][1][i][0], ap[mi][i], b1.x);
                    fma2(acc[mi][1][i][1], ap[mi][i], b1.y);
                }
        }

        #pragma unroll
        for (int mi = 0; mi < 2; mi++)
            #pragma unroll
            for (int i = 0; i < 4; i++) {
                const int m  = mi*64 + ty*4 + i;
                const int qg = q0 + m;
                const float* brow = &sh_bias[m*7];
                #pragma unroll
                for (int g = 0; g < 2; g++) {
                    float2 u0 = unp(acc[mi][g][i][0]);
                    float2 u1 = unp(acc[mi][g][i][1]);
                    float vv[4] = {u0.x, u0.y, u1.x, u1.y};
                    float o[4];
                    #pragma unroll
                    for (int c = 0; c < 4; c++) {
                        int kg  = k0 + g*64 + tx*4 + c;
                        int dlt = kg - qg;
                        int rr  = dlt < -3 ? 0 : (dlt > 3 ? 6 : dlt + 3);
                        float s = 8.f * (vv[c] + brow[rr]);
                        o[c] = s;
                        pmax[mi][i] = fmaxf(pmax[mi][i], s);
                    }
                    *(float4*)(attn_base + (size_t)m*L_ + k0 + g*64 + tx*4)
                        = make_float4(o[0], o[1], o[2], o[3]);
                }
            }
        __syncthreads();
    }

    // ---- row-max reduce over the 16 tx lanes ----
    #pragma unroll
    for (int mi = 0; mi < 2; mi++)
        #pragma unroll
        for (int i = 0; i < 4; i++) {
            float v = pmax[mi][i];
            #pragma unroll
            for (int off = 8; off > 0; off >>= 1)
                v = fmaxf(v, __shfl_xor_sync(0xffffffffu, v, off));
            if (tx == 0) sh_rowmax[mi*64 + ty*4 + i] = v;
        }
    __syncthreads();

    // ================= pass 2: exp + sums + PV (k-split-2) =================
    const int g    = tid >> 7;       // 0/1: k-split group
    const int t2   = tid & 127;
    const int txd  = t2 & 7;         // 8 d's per thread
    const int tym  = t2 >> 3;        // 16 m-groups

    const int m2   = lrow;           // exp-stage row
    const int c0   = lk4;
    const int qg2  = q0 + m2;
    const float rm2 = sh_rowmax[m2];

    float tsum = 0.f, s0sum = 0.f, s6sum = 0.f;
    u64 wacc[2][4][4] = {};

    for (int kc = 0; kc < NCH_; kc++) {
        const int k0 = kc * TK_;
        // V loader (row-major, coalesced, conflict-free)
        #pragma unroll
        for (int r = 0; r < 8; r++) {
            int n = r*16 + ty;
            float4 v = *(const float4*)(vbase + (size_t)(k0 + n)*D_ + tx*4);
            *(float4*)&Vs[n*68 + tx*4] = v;
        }
        // exp stage: row m2, cols c0 + 8r; transposed STS with 2-way mapping
        #pragma unroll
        for (int r = 0; r < 16; r++) {
            int c = c0 + 8*r;
            float4 sv = *(const float4*)(attn_base + (size_t)m2*L_ + k0 + c);
            float svv[4] = {sv.x, sv.y, sv.z, sv.w};
            #pragma unroll
            for (int j = 0; j < 4; j++) {
                float e = __expf(svv[j] - rm2);
                tsum += e;
                int dlt = k0 + c + j - qg2;
                if (dlt <= -3)      s0sum += e;
                else if (dlt >= 3)  s6sum += e;
                else                sh_pmid[m2*5 + dlt + 2] = e;
                Es[(c+j)*132 + m2] = e;
            }
        }
        __syncthreads();
        // PV: each group handles 64 k's with 8x8 micro-tile
        #pragma unroll 4
        for (int kk = 0; kk < 64; kk++) {
            int k = g*64 + kk;
            float4 e0 = *(const float4*)&Es[k*132 + tym*4];
            float4 e1 = *(const float4*)&Es[k*132 + 64 + tym*4];
            ulonglong2 v0 = *(const ulonglong2*)&Vs[k*68 + txd*8];
            ulonglong2 v1 = *(const ulonglong2*)&Vs[k*68 + txd*8 + 4];
            u64 ep[2][4] = {{pack2(e0.x), pack2(e0.y), pack2(e0.z), pack2(e0.w)},
                            {pack2(e1.x), pack2(e1.y), pack2(e1.z), pack2(e1.w)}};
            #pragma unroll
            for (int mi = 0; mi < 2; mi++)
                #pragma unroll
                for (int i = 0; i < 4; i++) {
                    fma2(wacc[mi][i][0], ep[mi][i], v0.x);
                    fma2(wacc[mi][i][1], ep[mi][i], v0.y);
                    fma2(wacc[mi][i][2], ep[mi][i], v1.x);
                    fma2(wacc[mi][i][3], ep[mi][i], v1.y);
                }
        }
        __syncthreads();
    }

    // ---- row-sum pair reduce (two threads per row) ----
    tsum  += __shfl_xor_sync(0xffffffffu, tsum,  1);
    s0sum += __shfl_xor_sync(0xffffffffu, s0sum, 1);
    s6sum += __shfl_xor_sync(0xffffffffu, s6sum, 1);
    if ((tid & 1) == 0) { sh_T[m2] = tsum; sh_S0[m2] = s0sum; sh_S6[m2] = s6sum; }
    __syncthreads();

    // ---- k-split pair reduce via smem (reuse Es region) ----
    if (g == 1) {
        #pragma unroll
        for (int mi = 0; mi < 2; mi++)
            #pragma unroll
            for (int i = 0; i < 4; i++)
                #pragma unroll
                for (int p = 0; p < 4; p++)
                    *(u64*)&dsm[t2*64 + ((mi*4 + i)*4 + p)*2] = wacc[mi][i][p];
    }
    __syncthreads();
    if (g == 0) {
        #pragma unroll
        for (int mi = 0; mi < 2; mi++)
            #pragma unroll
            for (int i = 0; i < 4; i++)
                #pragma unroll
                for (int p = 0; p < 4; p++)
                    add2(wacc[mi][i][p], *(const u64*)&dsm[t2*64 + ((mi*4 + i)*4 + p)*2]);

        // ---- w = (w1 + w2) * invT -> scratch [B,L,H,hd] ----
        float* wbase = gw + ((size_t)(b*L_ + q0))*D_ + h*HD_;
        #pragma unroll
        for (int mi = 0; mi < 2; mi++)
            #pragma unroll
            for (int i = 0; i < 4; i++) {
                const int m = mi*64 + tym*4 + i;
                float T  = sh_T[m];
                float S0 = sh_S0[m];
                float S6 = sh_S6[m];
                float inv = 1.f / T;
                float mids[5];
                #pragma unroll
                for (int r = 0; r < 5; r++) mids[r] = sh_pmid[m*5 + r];
                float o[8];
                #pragma unroll
                for (int p = 0; p < 4; p++) {
                    float2 u = unp(wacc[mi][i][p]);
                    o[2*p] = u.x; o[2*p + 1] = u.y;
                }
                #pragma unroll
                for (int j = 0; j < 8; j++) {
                    int d = txd*8 + j;
                    float w2 = S0 * sh_relv[d] + S6 * sh_relv[6*HD_ + d];
                    #pragma unroll
                    for (int r = 0; r < 5; r++)
                        w2 = fmaf(mids[r], sh_relv[(r+1)*HD_ + d], w2);
                    o[j] = (o[j] + w2) * inv;
                }
                *(float4*)(wbase + (size_t)m*D_ + txd*8)     = make_float4(o[0], o[1], o[2], o[3]);
                *(float4*)(wbase + (size_t)m*D_ + txd*8 + 4) = make_float4(o[4], o[5], o[6], o[7]);
            }
    }

    // ================= pass 3: normalized attn out =================
    const float inv3 = 1.f / sh_T[m2];
    #pragma unroll 4
    for (int r = 0; r < 128; r++) {
        int c = c0 + 8*r;
        float* p = attn_base + (size_t)m2*L_ + c;
        float4 a = *(const float4*)p;
        a.x = __expf(a.x - rm2) * inv3;
        a.y = __expf(a.y - rm2) * inv3;
        a.z = __expf(a.z - rm2) * inv3;
        a.w = __expf(a.w - rm2) * inv3;
        *(float4*)p = a;
    }
}

// ---------------- launch ----------------
extern "C" void kernel_launch(void* const* d_in, const int* in_sizes, int n_in,
                              void* d_out, int out_size)
{
    const float* query  = (const float*)d_in[0];
    const float* key    = (const float*)d_in[1];
    const float* value  = (const float*)d_in[2];
    const float* Wq     = (const float*)d_in[3];
    const float* Wk     = (const float*)d_in[4];
    const float* Wv     = (const float*)d_in[5];
    const float* Wproj  = (const float*)d_in[6];
    const float* b_proj = (const float*)d_in[7];
    const float* relk   = (const float*)d_in[8];
    const float* relv   = (const float*)d_in[9];

    float* out  = (float*)d_out;
    float* attn = out + (size_t)B_ * L_ * D_;   // x first, then attn

    float *gq, *gk, *gv, *gw;
    cudaGetSymbolAddress((void**)&gq, g_q);
    cudaGetSymbolAddress((void**)&gk, g_k);
    cudaGetSymbolAddress((void**)&gv, g_v);
    cudaGetSymbolAddress((void**)&gw, g_w);

    cudaFuncSetAttribute(attn_kernel, cudaFuncAttributeMaxDynamicSharedMemorySize,
                         DYN_SMEM_BYTES);

    mma_qkv_kernel<<<dim3(36, 32), 256>>>(query, key, value, Wq, Wk, Wv, gq, gk, gv);

    attn_kernel<<<dim3(L_/TQ_, H_, B_), 256, DYN_SMEM_BYTES>>>(
        gq, gk, gv, relk, relv, attn, gw);

    mma_proj_kernel<<<dim3(12, 32), 256>>>(gw, Wproj, b_proj, out);
}

// round 13
// speedup vs baseline: 1.4283x; 1.0213x over previous
#include <cuda_runtime.h>
#include <math.h>
#include <stdint.h>

typedef unsigned long long u64;

static constexpr int B_  = 4;
static constexpr int L_  = 1024;
static constexpr int D_  = 768;
static constexpr int H_  = 12;
static constexpr int HD_ = 64;
static constexpr int TQ_ = 128;
static constexpr int TK_ = 128;
static constexpr int NCH_ = L_ / TK_;   // 8

// attn dynamic smem (pass2 dominates): Es[128][132] + Vs[128][68]
static constexpr int DYN_SMEM_BYTES = (128*132 + 128*68) * 4;   // 100352

// mma GEMM config
static constexpr int KT  = 16;          // k-tile
static constexpr int NKT = D_ / KT;     // 48
static constexpr int PAD = 20;          // floats per smem row (16 used)

// ---------------- packed f32x2 helpers (attn pass2) ----------------
__device__ __forceinline__ u64 pack2(float v) {
    u64 r; asm("mov.b64 %0, {%1, %1};" : "=l"(r) : "f"(v)); return r;
}
__device__ __forceinline__ void fma2(u64& c, u64 a, u64 b) {
    asm("fma.rn.f32x2 %0, %1, %2, %0;" : "+l"(c) : "l"(a), "l"(b));
}
__device__ __forceinline__ void add2(u64& c, u64 a) {
    asm("add.rn.f32x2 %0, %0, %1;" : "+l"(c) : "l"(a));
}
__device__ __forceinline__ float2 unp(u64 v) {
    float2 f; asm("mov.b64 {%0, %1}, %2;" : "=f"(f.x), "=f"(f.y) : "l"(v)); return f;
}

// ---------------- mma.sync helpers ----------------
__device__ __forceinline__ uint32_t smem_u32(const void* p) {
    uint32_t a;
    asm("{ .reg .u64 t; cvta.to.shared.u64 t, %1; cvt.u32.u64 %0, t; }"
        : "=r"(a) : "l"(p));
    return a;
}
__device__ __forceinline__ float tf32_rna(float x) {
    uint32_t r; asm("cvt.rna.tf32.f32 %0, %1;" : "=r"(r) : "f"(x));
    return __uint_as_float(r);
}
__device__ __forceinline__ void ldsm4(uint32_t r[4], uint32_t a) {
    asm volatile("ldmatrix.sync.aligned.m8n8.x4.shared.b16 {%0,%1,%2,%3}, [%4];"
        : "=r"(r[0]), "=r"(r[1]), "=r"(r[2]), "=r"(r[3]) : "r"(a));
}
__device__ __forceinline__ void ldsm2(uint32_t r[2], uint32_t a) {
    asm volatile("ldmatrix.sync.aligned.m8n8.x2.shared.b16 {%0,%1}, [%2];"
        : "=r"(r[0]), "=r"(r[1]) : "r"(a));
}
__device__ __forceinline__ void mma8(float c[4], const uint32_t a[4],
                                     const uint32_t b[2]) {
    asm volatile(
        "mma.sync.aligned.m16n8k8.row.col.f32.tf32.tf32.f32 "
        "{%0,%1,%2,%3}, {%4,%5,%6,%7}, {%8,%9}, {%0,%1,%2,%3};"
        : "+f"(c[0]), "+f"(c[1]), "+f"(c[2]), "+f"(c[3])
        : "r"(a[0]), "r"(a[1]), "r"(a[2]), "r"(a[3]), "r"(b[0]), "r"(b[1]));
}
// split a float4 into tf32 hi / fp32 residual lo
__device__ __forceinline__ void split4(float4 v, float4& h, float4& l) {
    h.x = tf32_rna(v.x); l.x = v.x - h.x;
    h.y = tf32_rna(v.y); l.y = v.y - h.y;
    h.z = tf32_rna(v.z); l.z = v.z - h.z;
    h.w = tf32_rna(v.w); l.w = v.w - h.w;
}

// ---------------- device scratch ----------------
__device__ float g_q[(size_t)B_ * L_ * D_];
__device__ float g_k[(size_t)B_ * L_ * D_];
__device__ float g_v[(size_t)B_ * L_ * D_];
__device__ float g_w[(size_t)B_ * L_ * D_];

// ---------------- split-tf32 mma.sync GEMM: C[128,128] tile of A@W^T -----
// 8 warps: 4 wy (m) x 2 wx (n); warp tile 32m x 64n.
__device__ __forceinline__ void mma_gemm_tile128(const float* __restrict__ A,
                                                 const float* __restrict__ W,
                                                 const float* __restrict__ bias,
                                                 float* __restrict__ C,
                                                 int m0, int n0)
{
    __shared__ float Ah[128*PAD], Al[128*PAD], Bh[128*PAD], Bl[128*PAD];

    const int tid  = threadIdx.x;
    const int lane = tid & 31, wid = tid >> 5;
    const int wy = wid & 3, wx = wid >> 2;
    const int gid = lane >> 2, tig = lane & 3;

    const int rowL = tid >> 1, khL = (tid & 1) * 8;
    const float* Ap = A + (size_t)(m0 + rowL) * D_ + khL;
    const float* Wp = W + (size_t)(n0 + rowL) * D_ + khL;

    // ldmatrix addresses
    uint32_t aAh[2], aAl[2], aBh, aBl;
    {
        int r  = 32*wy + (lane & 7) + 8*((lane >> 3) & 1);
        int kc = 4 * (lane >> 4);
        aAh[0] = smem_u32(&Ah[r*PAD + kc]);
        aAh[1] = aAh[0] + 16*PAD*4;
        aAl[0] = smem_u32(&Al[r*PAD + kc]);
        aAl[1] = aAl[0] + 16*PAD*4;
        int rB  = 64*wx + (lane & 7);
        int kcB = 4 * ((lane >> 3) & 1);
        aBh = smem_u32(&Bh[rB*PAD + kcB]);
        aBl = smem_u32(&Bl[rB*PAD + kcB]);
    }

    float c[2][8][4] = {};

    float4 va0 = *(const float4*)(Ap);
    float4 va1 = *(const float4*)(Ap + 4);
    float4 vb0 = *(const float4*)(Wp);
    float4 vb1 = *(const float4*)(Wp + 4);

    for (int kt = 0; kt < NKT; kt++) {
        {
            float4 h, l;
            split4(va0, h, l);
            *(float4*)&Ah[rowL*PAD + khL] = h; *(float4*)&Al[rowL*PAD + khL] = l;
            split4(va1, h, l);
            *(float4*)&Ah[rowL*PAD + khL + 4] = h; *(float4*)&Al[rowL*PAD + khL + 4] = l;
            split4(vb0, h, l);
            *(float4*)&Bh[rowL*PAD + khL] = h; *(float4*)&Bl[rowL*PAD + khL] = l;
            split4(vb1, h, l);
            *(float4*)&Bh[rowL*PAD + khL + 4] = h; *(float4*)&Bl[rowL*PAD + khL + 4] = l;
        }
        __syncthreads();
        if (kt + 1 < NKT) {
            va0 = *(const float4*)(Ap + (kt+1)*KT);
            va1 = *(const float4*)(Ap + (kt+1)*KT + 4);
            vb0 = *(const float4*)(Wp + (kt+1)*KT);
            vb1 = *(const float4*)(Wp + (kt+1)*KT + 4);
        }
        #pragma unroll
        for (int k8 = 0; k8 < 2; k8++) {
            const uint32_t ko = (uint32_t)(k8 * 32);
            uint32_t ah[2][4], al[2][4];
            ldsm4(ah[0], aAh[0] + ko);
            ldsm4(ah[1], aAh[1] + ko);
            ldsm4(al[0], aAl[0] + ko);
            ldsm4(al[1], aAl[1] + ko);
            #pragma unroll
            for (int nj = 0; nj < 8; nj++) {
                uint32_t bh[2], bl[2];
                ldsm2(bh, aBh + (uint32_t)(nj*8*PAD*4) + ko);
                ldsm2(bl, aBl + (uint32_t)(nj*8*PAD*4) + ko);
                #pragma unroll
                for (int mi = 0; mi < 2; mi++) {
                    mma8(c[mi][nj], ah[mi], bh);
                    mma8(c[mi][nj], ah[mi], bl);
                    mma8(c[mi][nj], al[mi], bh);
                }
            }
        }
        __syncthreads();
    }

    // epilogue: fragment-direct float2 stores
    #pragma unroll
    for (int mi = 0; mi < 2; mi++) {
        const int r0 = m0 + 32*wy + 16*mi + gid;
        #pragma unroll
        for (int nj = 0; nj < 8; nj++) {
            const int cc = n0 + 64*wx + 8*nj + 2*tig;
            float2 v0 = make_float2(c[mi][nj][0], c[mi][nj][1]);
            float2 v1 = make_float2(c[mi][nj][2], c[mi][nj][3]);
            if (bias) {
                float bx = bias[cc], by = bias[cc+1];
                v0.x += bx; v0.y += by;
                v1.x += bx; v1.y += by;
            }
            *(float2*)&C[(size_t)r0 * D_ + cc]       = v0;
            *(float2*)&C[(size_t)(r0 + 8) * D_ + cc] = v1;
        }
    }
}

__global__ __launch_bounds__(256)
void mma_qkv_kernel(const float* __restrict__ Aq, const float* __restrict__ Ak,
                    const float* __restrict__ Av,
                    const float* __restrict__ Wq, const float* __restrict__ Wk,
                    const float* __restrict__ Wv,
                    float* __restrict__ Cq, float* __restrict__ Ck,
                    float* __restrict__ Cv)
{
    const int sel = blockIdx.x / 6;
    const int n0  = (blockIdx.x % 6) * 128;
    const int m0  = blockIdx.y * 128;
    const float* A = (sel == 0) ? Aq : (sel == 1) ? Ak : Av;
    const float* W = (sel == 0) ? Wq : (sel == 1) ? Wk : Wv;
    float*       C = (sel == 0) ? Cq : (sel == 1) ? Ck : Cv;
    mma_gemm_tile128(A, W, nullptr, C, m0, n0);
}

__global__ __launch_bounds__(256)
void mma_proj_kernel(const float* __restrict__ A, const float* __restrict__ W,
                     const float* __restrict__ bias, float* __restrict__ C)
{
    mma_gemm_tile128(A, W, bias, C, blockIdx.y * 128, blockIdx.x * 128);
}

// ---------------- attention: mma pass-1 + champion pass-2/3 --------------
__global__ __launch_bounds__(256, 2)
void attn_kernel(const float* __restrict__ gq, const float* __restrict__ gk,
                 const float* __restrict__ gv,
                 const float* __restrict__ relk, const float* __restrict__ relv,
                 float* __restrict__ attn, float* __restrict__ gw)
{
    extern __shared__ float dsm[];
    // pass1 views (10240 floats)
    float* Qh = dsm;
    float* Ql = dsm + 128*PAD;
    float* Kh = dsm + 2*128*PAD;
    float* Kl = dsm + 3*128*PAD;
    // pass2 views (overlap)
    float* Es = dsm;              // [128][132] k-major
    float* Vs = dsm + 128*132;    // [128][68]  row-major

    __shared__ float sh_relk[7*HD_];
    __shared__ float sh_relv[7*HD_];
    __shared__ float sh_bias[TQ_*7];
    __shared__ float sh_rowmax[TQ_];
    __shared__ float sh_red[TQ_*2];
    __shared__ float sh_T[TQ_];
    __shared__ float sh_S0[TQ_];
    __shared__ float sh_S6[TQ_];
    __shared__ float sh_pmid[TQ_*5];

    const int qq0 = blockIdx.x * TQ_;
    const int h   = blockIdx.y;
    const int b   = blockIdx.z;
    const int tid = threadIdx.x;
    const int tx  = tid & 15, ty = tid >> 4;
    const int lrow = tid >> 1;          // 0..127
    const int lk4  = (tid & 1) * 4;

    for (int i = tid; i < 7*HD_; i += 256) { sh_relk[i] = relk[i]; sh_relv[i] = relv[i]; }
    for (int i = tid; i < TQ_*5; i += 256) sh_pmid[i] = 0.f;
    __syncthreads();   // relk fully loaded before ANY thread computes bias

    const float* qbase = gq + ((size_t)(b*L_ + qq0))*D_ + h*HD_;
    const float* kbase = gk + ((size_t)b*L_)*D_ + h*HD_;
    const float* vbase = gv + ((size_t)b*L_)*D_ + h*HD_;
    float* attn_base = attn + (((size_t)(b*H_ + h))*L_ + qq0) * L_;

    // ---- rel-k bias from gmem (L2-hot): bias[m][r] = Q[m] . rel_k[r] ----
    for (int idx = tid; idx < TQ_*7; idx += 256) {
        int m = idx / 7, rr = idx % 7;
        float s = 0.f;
        #pragma unroll
        for (int d = 0; d < HD_; d++)
            s = fmaf(qbase[(size_t)m*D_ + d], sh_relk[rr*HD_ + d], s);
        sh_bias[idx] = s;
    }
    __syncthreads();   // bias visible before pass-1 epilogue reads

    // ================= pass 1: logits via split-tf32 mma =================
    const int lane = tid & 31, wid = tid >> 5;
    const int wy = wid & 3, wx = wid >> 2;
    const int gid = lane >> 2, tig = lane & 3;
    const int rowL = tid >> 1, khL = (tid & 1) * 8;

    uint32_t aQh[2], aQl[2], aKh, aKl;
    {
        int r  = 32*wy + (lane & 7) + 8*((lane >> 3) & 1);
        int kc = 4 * (lane >> 4);
        aQh[0] = smem_u32(&Qh[r*PAD + kc]);
        aQh[1] = aQh[0] + 16*PAD*4;
        aQl[0] = smem_u32(&Ql[r*PAD + kc]);
        aQl[1] = aQl[0] + 16*PAD*4;
        int rB  = 64*wx + (lane & 7);
        int kcB = 4 * ((lane >> 3) & 1);
        aKh = smem_u32(&Kh[rB*PAD + kcB]);
        aKl = smem_u32(&Kl[rB*PAD + kcB]);
    }

    float pm[2][2];
    pm[0][0] = pm[0][1] = pm[1][0] = pm[1][1] = -1e30f;

    for (int kc = 0; kc < NCH_; kc++) {
        const int k0 = kc * TK_;
        float c[2][8][4] = {};
        #pragma unroll
        for (int kt = 0; kt < 4; kt++) {
            // stage Q/K d16-chunk, split hi/lo
            {
                float4 q0 = *(const float4*)(qbase + (size_t)rowL*D_ + kt*16 + khL);
                float4 q1 = *(const float4*)(qbase + (size_t)rowL*D_ + kt*16 + khL + 4);
                float4 kv0 = *(const float4*)(kbase + (size_t)(k0 + rowL)*D_ + kt*16 + khL);
                float4 kv1 = *(const float4*)(kbase + (size_t)(k0 + rowL)*D_ + kt*16 + khL + 4);
                float4 hh, ll;
                split4(q0, hh, ll);
                *(float4*)&Qh[rowL*PAD + khL] = hh; *(float4*)&Ql[rowL*PAD + khL] = ll;
                split4(q1, hh, ll);
                *(float4*)&Qh[rowL*PAD + khL + 4] = hh; *(float4*)&Ql[rowL*PAD + khL + 4] = ll;
                split4(kv0, hh, ll);
                *(float4*)&Kh[rowL*PAD + khL] = hh; *(float4*)&Kl[rowL*PAD + khL] = ll;
                split4(kv1, hh, ll);
                *(float4*)&Kh[rowL*PAD + khL + 4] = hh; *(float4*)&Kl[rowL*PAD + khL + 4] = ll;
            }
            __syncthreads();
            #pragma unroll
            for (int k8 = 0; k8 < 2; k8++) {
                const uint32_t ko = (uint32_t)(k8 * 32);
                uint32_t ah[2][4], al[2][4];
                ldsm4(ah[0], aQh[0] + ko);
                ldsm4(ah[1], aQh[1] + ko);
                ldsm4(al[0], aQl[0] + ko);
                ldsm4(al[1], aQl[1] + ko);
                #pragma unroll
                for (int nj = 0; nj < 8; nj++) {
                    uint32_t bh[2], bl[2];
                    ldsm2(bh, aKh + (uint32_t)(nj*8*PAD*4) + ko);
                    ldsm2(bl, aKl + (uint32_t)(nj*8*PAD*4) + ko);
                    #pragma unroll
                    for (int mi = 0; mi < 2; mi++) {
                        mma8(c[mi][nj], ah[mi], bh);
                        mma8(c[mi][nj], ah[mi], bl);
                        mma8(c[mi][nj], al[mi], bh);
                    }
                }
            }
            __syncthreads();
        }
        // ---- epilogue: bias + scale + rowmax + raw-S store ----
        #pragma unroll
        for (int mi = 0; mi < 2; mi++) {
            #pragma unroll
            for (int half = 0; half < 2; half++) {
                const int m  = 32*wy + 16*mi + 8*half + gid;
                const int qg = qq0 + m;
                const float* brow = &sh_bias[m*7];
                float mx = pm[mi][half];
                #pragma unroll
                for (int nj = 0; nj < 8; nj++) {
                    const int kg = k0 + 64*wx + 8*nj + 2*tig;
                    int d0 = kg - qg, d1 = d0 + 1;
                    int r0 = d0 < -3 ? 0 : (d0 > 3 ? 6 : d0 + 3);
                    int r1 = d1 < -3 ? 0 : (d1 > 3 ? 6 : d1 + 3);
                    float s0 = 8.f * (c[mi][nj][2*half]     + brow[r0]);
                    float s1 = 8.f * (c[mi][nj][2*half + 1] + brow[r1]);
                    mx = fmaxf(mx, fmaxf(s0, s1));
                    *(float2*)&attn_base[(size_t)m*L_ + kg] = make_float2(s0, s1);
                }
                pm[mi][half] = mx;
            }
        }
    }

    // ---- rowmax reduce: tig lanes, then wx warps ----
    #pragma unroll
    for (int mi = 0; mi < 2; mi++)
        #pragma unroll
        for (int half = 0; half < 2; half++) {
            float v = pm[mi][half];
            v = fmaxf(v, __shfl_xor_sync(0xffffffffu, v, 1));
            v = fmaxf(v, __shfl_xor_sync(0xffffffffu, v, 2));
            if (tig == 0)
                sh_red[(32*wy + 16*mi + 8*half + gid)*2 + wx] = v;
        }
    __syncthreads();
    if (tid < TQ_) sh_rowmax[tid] = fmaxf(sh_red[tid*2], sh_red[tid*2 + 1]);
    __syncthreads();

    // ================= pass 2: exp + sums + PV (champion) =================
    const int g    = tid >> 7;
    const int t2   = tid & 127;
    const int txd  = t2 & 7;
    const int tym  = t2 >> 3;

    const int m2   = lrow;
    const int c0   = lk4;
    const int qg2  = qq0 + m2;
    const float rm2 = sh_rowmax[m2];

    float tsum = 0.f, s0sum = 0.f, s6sum = 0.f;
    u64 wacc[2][4][4] = {};

    for (int kc = 0; kc < NCH_; kc++) {
        const int k0 = kc * TK_;
        #pragma unroll
        for (int r = 0; r < 8; r++) {
            int n = r*16 + ty;
            float4 v = *(const float4*)(vbase + (size_t)(k0 + n)*D_ + tx*4);
            *(float4*)&Vs[n*68 + tx*4] = v;
        }
        #pragma unroll
        for (int r = 0; r < 16; r++) {
            int c = c0 + 8*r;
            float4 sv = *(const float4*)(attn_base + (size_t)m2*L_ + k0 + c);
            float svv[4] = {sv.x, sv.y, sv.z, sv.w};
            #pragma unroll
            for (int j = 0; j < 4; j++) {
                float e = __expf(svv[j] - rm2);
                tsum += e;
                int dlt = k0 + c + j - qg2;
                if (dlt <= -3)      s0sum += e;
                else if (dlt >= 3)  s6sum += e;
                else                sh_pmid[m2*5 + dlt + 2] = e;
                Es[(c+j)*132 + m2] = e;
            }
        }
        __syncthreads();
        #pragma unroll 4
        for (int kk = 0; kk < 64; kk++) {
            int k = g*64 + kk;
            float4 e0 = *(const float4*)&Es[k*132 + tym*4];
            float4 e1 = *(const float4*)&Es[k*132 + 64 + tym*4];
            ulonglong2 v0 = *(const ulonglong2*)&Vs[k*68 + txd*8];
            ulonglong2 v1 = *(const ulonglong2*)&Vs[k*68 + txd*8 + 4];
            u64 ep[2][4] = {{pack2(e0.x), pack2(e0.y), pack2(e0.z), pack2(e0.w)},
                            {pack2(e1.x), pack2(e1.y), pack2(e1.z), pack2(e1.w)}};
            #pragma unroll
            for (int mi = 0; mi < 2; mi++)
                #pragma unroll
                for (int i = 0; i < 4; i++) {
                    fma2(wacc[mi][i][0], ep[mi][i], v0.x);
                    fma2(wacc[mi][i][1], ep[mi][i], v0.y);
                    fma2(wacc[mi][i][2], ep[mi][i], v1.x);
                    fma2(wacc[mi][i][3], ep[mi][i], v1.y);
                }
        }
        __syncthreads();
    }

    tsum  += __shfl_xor_sync(0xffffffffu, tsum,  1);
    s0sum += __shfl_xor_sync(0xffffffffu, s0sum, 1);
    s6sum += __shfl_xor_sync(0xffffffffu, s6sum, 1);
    if ((tid & 1) == 0) { sh_T[m2] = tsum; sh_S0[m2] = s0sum; sh_S6[m2] = s6sum; }
    __syncthreads();

    if (g == 1) {
        #pragma unroll
        for (int mi = 0; mi < 2; mi++)
            #pragma unroll
            for (int i = 0; i < 4; i++)
                #pragma unroll
                for (int p = 0; p < 4; p++)
                    *(u64*)&dsm[t2*64 + ((mi*4 + i)*4 + p)*2] = wacc[mi][i][p];
    }
    __syncthreads();
    if (g == 0) {
        #pragma unroll
        for (int mi = 0; mi < 2; mi++)
            #pragma unroll
            for (int i = 0; i < 4; i++)
                #pragma unroll
                for (int p = 0; p < 4; p++)
                    add2(wacc[mi][i][p], *(const u64*)&dsm[t2*64 + ((mi*4 + i)*4 + p)*2]);

        float* wbase = gw + ((size_t)(b*L_ + qq0))*D_ + h*HD_;
        #pragma unroll
        for (int mi = 0; mi < 2; mi++)
            #pragma unroll
            for (int i = 0; i < 4; i++) {
                const int m = mi*64 + tym*4 + i;
                float T  = sh_T[m];
                float S0 = sh_S0[m];
                float S6 = sh_S6[m];
                float inv = 1.f / T;
                float mids[5];
                #pragma unroll
                for (int r = 0; r < 5; r++) mids[r] = sh_pmid[m*5 + r];
                float o[8];
                #pragma unroll
                for (int p = 0; p < 4; p++) {
                    float2 u = unp(wacc[mi][i][p]);
                    o[2*p] = u.x; o[2*p + 1] = u.y;
                }
                #pragma unroll
                for (int j = 0; j < 8; j++) {
                    int d = txd*8 + j;
                    float w2 = S0 * sh_relv[d] + S6 * sh_relv[6*HD_ + d];
                    #pragma unroll
                    for (int r = 0; r < 5; r++)
                        w2 = fmaf(mids[r], sh_relv[(r+1)*HD_ + d], w2);
                    o[j] = (o[j] + w2) * inv;
                }
                *(float4*)(wbase + (size_t)m*D_ + txd*8)     = make_float4(o[0], o[1], o[2], o[3]);
                *(float4*)(wbase + (size_t)m*D_ + txd*8 + 4) = make_float4(o[4], o[5], o[6], o[7]);
            }
    }

    // ================= pass 3: normalized attn out =================
    const float inv3 = 1.f / sh_T[m2];
    #pragma unroll 4
    for (int r = 0; r < 128; r++) {
        int c = c0 + 8*r;
        float* p = attn_base + (size_t)m2*L_ + c;
        float4 a = *(const float4*)p;
        a.x = __expf(a.x - rm2) * inv3;
        a.y = __expf(a.y - rm2) * inv3;
        a.z = __expf(a.z - rm2) * inv3;
        a.w = __expf(a.w - rm2) * inv3;
        *(float4*)p = a;
    }
}

// ---------------- launch ----------------
extern "C" void kernel_launch(void* const* d_in, const int* in_sizes, int n_in,
                              void* d_out, int out_size)
{
    const float* query  = (const float*)d_in[0];
    const float* key    = (const float*)d_in[1];
    const float* value  = (const float*)d_in[2];
    const float* Wq     = (const float*)d_in[3];
    const float* Wk     = (const float*)d_in[4];
    const float* Wv     = (const float*)d_in[5];
    const float* Wproj  = (const float*)d_in[6];
    const float* b_proj = (const float*)d_in[7];
    const float* relk   = (const float*)d_in[8];
    const float* relv   = (const float*)d_in[9];

    float* out  = (float*)d_out;
    float* attn = out + (size_t)B_ * L_ * D_;   // x first, then attn

    float *gq, *gk, *gv, *gw;
    cudaGetSymbolAddress((void**)&gq, g_q);
    cudaGetSymbolAddress((void**)&gk, g_k);
    cudaGetSymbolAddress((void**)&gv, g_v);
    cudaGetSymbolAddress((void**)&gw, g_w);

    cudaFuncSetAttribute(attn_kernel, cudaFuncAttributeMaxDynamicSharedMemorySize,
                         DYN_SMEM_BYTES);

    mma_qkv_kernel<<<dim3(18, 32), 256>>>(query, key, value, Wq, Wk, Wv, gq, gk, gv);

    attn_kernel<<<dim3(L_/TQ_, H_, B_), 256, DYN_SMEM_BYTES>>>(
        gq, gk, gv, relk, relv, attn, gw);

    mma_proj_kernel<<<dim3(6, 32), 256>>>(gw, Wproj, b_proj, out);
}

// round 14
// speedup vs baseline: 1.5266x; 1.0688x over previous
#include <cuda_runtime.h>
#include <math.h>
#include <stdint.h>

typedef unsigned long long u64;

static constexpr int B_  = 4;
static constexpr int L_  = 1024;
static constexpr int D_  = 768;
static constexpr int H_  = 12;
static constexpr int HD_ = 64;
static constexpr int TQ_ = 128;
static constexpr int TK_ = 128;
static constexpr int NCH_ = L_ / TK_;   // 8

// attn dynamic smem: pass1 Qh/Ql[128][68] + Kh/Kl[128][20] = 22528 floats
//                    pass2 Es[128][132] + Vs[64][68]       = 21248 floats
static constexpr int DYN_SMEM_BYTES = (2*128*68 + 2*128*20) * 4;   // 90112

// mma GEMM config
static constexpr int KT  = 16;          // k-tile
static constexpr int NKT = D_ / KT;     // 48
static constexpr int PAD = 20;          // floats per smem row (16 used)

// ---------------- mma.sync helpers ----------------
__device__ __forceinline__ uint32_t smem_u32(const void* p) {
    uint32_t a;
    asm("{ .reg .u64 t; cvta.to.shared.u64 t, %1; cvt.u32.u64 %0, t; }"
        : "=r"(a) : "l"(p));
    return a;
}
__device__ __forceinline__ float tf32_rna(float x) {
    uint32_t r; asm("cvt.rna.tf32.f32 %0, %1;" : "=r"(r) : "f"(x));
    return __uint_as_float(r);
}
__device__ __forceinline__ void ldsm4(uint32_t r[4], uint32_t a) {
    asm volatile("ldmatrix.sync.aligned.m8n8.x4.shared.b16 {%0,%1,%2,%3}, [%4];"
        : "=r"(r[0]), "=r"(r[1]), "=r"(r[2]), "=r"(r[3]) : "r"(a));
}
__device__ __forceinline__ void ldsm2(uint32_t r[2], uint32_t a) {
    asm volatile("ldmatrix.sync.aligned.m8n8.x2.shared.b16 {%0,%1}, [%2];"
        : "=r"(r[0]), "=r"(r[1]) : "r"(a));
}
__device__ __forceinline__ void mma8(float c[4], const uint32_t a[4],
                                     const uint32_t b[2]) {
    asm volatile(
        "mma.sync.aligned.m16n8k8.row.col.f32.tf32.tf32.f32 "
        "{%0,%1,%2,%3}, {%4,%5,%6,%7}, {%8,%9}, {%0,%1,%2,%3};"
        : "+f"(c[0]), "+f"(c[1]), "+f"(c[2]), "+f"(c[3])
        : "r"(a[0]), "r"(a[1]), "r"(a[2]), "r"(a[3]), "r"(b[0]), "r"(b[1]));
}
// split a float4 into tf32 hi / fp32 residual lo
__device__ __forceinline__ void split4(float4 v, float4& h, float4& l) {
    h.x = tf32_rna(v.x); l.x = v.x - h.x;
    h.y = tf32_rna(v.y); l.y = v.y - h.y;
    h.z = tf32_rna(v.z); l.z = v.z - h.z;
    h.w = tf32_rna(v.w); l.w = v.w - h.w;
}

// ---------------- device scratch ----------------
__device__ float g_q[(size_t)B_ * L_ * D_];
__device__ float g_k[(size_t)B_ * L_ * D_];
__device__ float g_v[(size_t)B_ * L_ * D_];
__device__ float g_w[(size_t)B_ * L_ * D_];

// ---------------- split-tf32 mma.sync GEMM: C[128,128] tile of A@W^T -----
// 8 warps: 4 wy (m) x 2 wx (n); warp tile 32m x 64n.  (R13 champion, unchanged)
__device__ __forceinline__ void mma_gemm_tile128(const float* __restrict__ A,
                                                 const float* __restrict__ W,
                                                 const float* __restrict__ bias,
                                                 float* __restrict__ C,
                                                 int m0, int n0)
{
    __shared__ float Ah[128*PAD], Al[128*PAD], Bh[128*PAD], Bl[128*PAD];

    const int tid  = threadIdx.x;
    const int lane = tid & 31, wid = tid >> 5;
    const int wy = wid & 3, wx = wid >> 2;
    const int gid = lane >> 2, tig = lane & 3;

    const int rowL = tid >> 1, khL = (tid & 1) * 8;
    const float* Ap = A + (size_t)(m0 + rowL) * D_ + khL;
    const float* Wp = W + (size_t)(n0 + rowL) * D_ + khL;

    uint32_t aAh[2], aAl[2], aBh, aBl;
    {
        int r  = 32*wy + (lane & 7) + 8*((lane >> 3) & 1);
        int kc = 4 * (lane >> 4);
        aAh[0] = smem_u32(&Ah[r*PAD + kc]);
        aAh[1] = aAh[0] + 16*PAD*4;
        aAl[0] = smem_u32(&Al[r*PAD + kc]);
        aAl[1] = aAl[0] + 16*PAD*4;
        int rB  = 64*wx + (lane & 7);
        int kcB = 4 * ((lane >> 3) & 1);
        aBh = smem_u32(&Bh[rB*PAD + kcB]);
        aBl = smem_u32(&Bl[rB*PAD + kcB]);
    }

    float c[2][8][4] = {};

    float4 va0 = *(const float4*)(Ap);
    float4 va1 = *(const float4*)(Ap + 4);
    float4 vb0 = *(const float4*)(Wp);
    float4 vb1 = *(const float4*)(Wp + 4);

    for (int kt = 0; kt < NKT; kt++) {
        {
            float4 h, l;
            split4(va0, h, l);
            *(float4*)&Ah[rowL*PAD + khL] = h; *(float4*)&Al[rowL*PAD + khL] = l;
            split4(va1, h, l);
            *(float4*)&Ah[rowL*PAD + khL + 4] = h; *(float4*)&Al[rowL*PAD + khL + 4] = l;
            split4(vb0, h, l);
            *(float4*)&Bh[rowL*PAD + khL] = h; *(float4*)&Bl[rowL*PAD + khL] = l;
            split4(vb1, h, l);
            *(float4*)&Bh[rowL*PAD + khL + 4] = h; *(float4*)&Bl[rowL*PAD + khL + 4] = l;
        }
        __syncthreads();
        if (kt + 1 < NKT) {
            va0 = *(const float4*)(Ap + (kt+1)*KT);
            va1 = *(const float4*)(Ap + (kt+1)*KT + 4);
            vb0 = *(const float4*)(Wp + (kt+1)*KT);
            vb1 = *(const float4*)(Wp + (kt+1)*KT + 4);
        }
        #pragma unroll
        for (int k8 = 0; k8 < 2; k8++) {
            const uint32_t ko = (uint32_t)(k8 * 32);
            uint32_t ah[2][4], al[2][4];
            ldsm4(ah[0], aAh[0] + ko);
            ldsm4(ah[1], aAh[1] + ko);
            ldsm4(al[0], aAl[0] + ko);
            ldsm4(al[1], aAl[1] + ko);
            #pragma unroll
            for (int nj = 0; nj < 8; nj++) {
                uint32_t bh[2], bl[2];
                ldsm2(bh, aBh + (uint32_t)(nj*8*PAD*4) + ko);
                ldsm2(bl, aBl + (uint32_t)(nj*8*PAD*4) + ko);
                #pragma unroll
                for (int mi = 0; mi < 2; mi++) {
                    mma8(c[mi][nj], ah[mi], bh);
                    mma8(c[mi][nj], ah[mi], bl);
                    mma8(c[mi][nj], al[mi], bh);
                }
            }
        }
        __syncthreads();
    }

    #pragma unroll
    for (int mi = 0; mi < 2; mi++) {
        const int r0 = m0 + 32*wy + 16*mi + gid;
        #pragma unroll
        for (int nj = 0; nj < 8; nj++) {
            const int cc = n0 + 64*wx + 8*nj + 2*tig;
            float2 v0 = make_float2(c[mi][nj][0], c[mi][nj][1]);
            float2 v1 = make_float2(c[mi][nj][2], c[mi][nj][3]);
            if (bias) {
                float bx = bias[cc], by = bias[cc+1];
                v0.x += bx; v0.y += by;
                v1.x += bx; v1.y += by;
            }
            *(float2*)&C[(size_t)r0 * D_ + cc]       = v0;
            *(float2*)&C[(size_t)(r0 + 8) * D_ + cc] = v1;
        }
    }
}

__global__ __launch_bounds__(256)
void mma_qkv_kernel(const float* __restrict__ Aq, const float* __restrict__ Ak,
                    const float* __restrict__ Av,
                    const float* __restrict__ Wq, const float* __restrict__ Wk,
                    const float* __restrict__ Wv,
                    float* __restrict__ Cq, float* __restrict__ Ck,
                    float* __restrict__ Cv)
{
    const int sel = blockIdx.x / 6;
    const int n0  = (blockIdx.x % 6) * 128;
    const int m0  = blockIdx.y * 128;
    const float* A = (sel == 0) ? Aq : (sel == 1) ? Ak : Av;
    const float* W = (sel == 0) ? Wq : (sel == 1) ? Wk : Wv;
    float*       C = (sel == 0) ? Cq : (sel == 1) ? Ck : Cv;
    mma_gemm_tile128(A, W, nullptr, C, m0, n0);
}

__global__ __launch_bounds__(256)
void mma_proj_kernel(const float* __restrict__ A, const float* __restrict__ W,
                     const float* __restrict__ bias, float* __restrict__ C)
{
    mma_gemm_tile128(A, W, bias, C, blockIdx.y * 128, blockIdx.x * 128);
}

// ---------------- attention: all-mma (S pass + PV pass) ------------------
__global__ __launch_bounds__(256, 2)
void attn_kernel(const float* __restrict__ gq, const float* __restrict__ gk,
                 const float* __restrict__ gv,
                 const float* __restrict__ relk, const float* __restrict__ relv,
                 float* __restrict__ attn, float* __restrict__ gw)
{
    extern __shared__ float dsm[];
    // pass1 views
    float* Qh = dsm;                        // [128][68]  (hoisted, full d=64)
    float* Ql = dsm + 128*68;               // [128][68]
    float* Kh = dsm + 2*128*68;             // [128][20]  per-kt slice
    float* Kl = dsm + 2*128*68 + 128*20;    // [128][20]
    // pass2 views (overlap)
    float* Es = dsm;                        // [128 m][132 k] row-major tf32
    float* Vs = dsm + 128*132;              // [64 k][68 d]  tf32 (half-chunk)

    __shared__ float sh_relk[7*HD_];
    __shared__ float sh_relv[7*HD_];
    __shared__ float sh_bias[TQ_*7];
    __shared__ float sh_rowmax[TQ_];
    __shared__ float sh_red[TQ_*2];
    __shared__ float sh_T[TQ_];
    __shared__ float sh_S0[TQ_];
    __shared__ float sh_S6[TQ_];
    __shared__ float sh_pmid[TQ_*5];

    const int qq0 = blockIdx.x * TQ_;
    const int h   = blockIdx.y;
    const int b   = blockIdx.z;
    const int tid = threadIdx.x;
    const int lrow = tid >> 1;          // 0..127
    const int lk4  = (tid & 1) * 4;

    for (int i = tid; i < 7*HD_; i += 256) { sh_relk[i] = relk[i]; sh_relv[i] = relv[i]; }
    for (int i = tid; i < TQ_*5; i += 256) sh_pmid[i] = 0.f;

    const float* qbase = gq + ((size_t)(b*L_ + qq0))*D_ + h*HD_;
    const float* kbase = gk + ((size_t)b*L_)*D_ + h*HD_;
    const float* vbase = gv + ((size_t)b*L_)*D_ + h*HD_;
    float* attn_base = attn + (((size_t)(b*H_ + h))*L_ + qq0) * L_;

    // ---- hoisted Q stage: split hi/lo into Qh/Ql[128][68] (once) ----
    {
        const int rowL = tid >> 1, khL = (tid & 1) * 8;
        #pragma unroll
        for (int t = 0; t < 4; t++) {
            int d = khL + 16*t;
            float4 q0 = *(const float4*)(qbase + (size_t)rowL*D_ + d);
            float4 q1 = *(const float4*)(qbase + (size_t)rowL*D_ + d + 4);
            float4 hh, ll;
            split4(q0, hh, ll);
            *(float4*)&Qh[rowL*68 + d] = hh; *(float4*)&Ql[rowL*68 + d] = ll;
            split4(q1, hh, ll);
            *(float4*)&Qh[rowL*68 + d + 4] = hh; *(float4*)&Ql[rowL*68 + d + 4] = ll;
        }
    }
    __syncthreads();   // relk loaded + Q staged

    // ---- rel-k bias: bias[m][r] = Q[m] . rel_k[r] ----
    for (int idx = tid; idx < TQ_*7; idx += 256) {
        int m = idx / 7, rr = idx % 7;
        float s = 0.f;
        #pragma unroll
        for (int d = 0; d < HD_; d++)
            s = fmaf(qbase[(size_t)m*D_ + d], sh_relk[rr*HD_ + d], s);
        sh_bias[idx] = s;
    }
    __syncthreads();

    // ================= pass 1: logits via split-tf32 mma =================
    const int lane = tid & 31, wid = tid >> 5;
    const int wy = wid & 3, wx = wid >> 2;
    const int gid = lane >> 2, tig = lane & 3;
    const int rowL = tid >> 1, khL = (tid & 1) * 8;

    uint32_t aQh[2], aQl[2], aKh, aKl;
    {
        int r  = 32*wy + (lane & 7) + 8*((lane >> 3) & 1);
        int kc = 4 * (lane >> 4);
        aQh[0] = smem_u32(&Qh[r*68 + kc]);
        aQh[1] = aQh[0] + 16*68*4;
        aQl[0] = smem_u32(&Ql[r*68 + kc]);
        aQl[1] = aQl[0] + 16*68*4;
        int rB  = 64*wx + (lane & 7);
        int kcB = 4 * ((lane >> 3) & 1);
        aKh = smem_u32(&Kh[rB*20 + kcB]);
        aKl = smem_u32(&Kl[rB*20 + kcB]);
    }

    float pm[2][2];
    pm[0][0] = pm[0][1] = pm[1][0] = pm[1][1] = -1e30f;

    for (int kc = 0; kc < NCH_; kc++) {
        const int k0 = kc * TK_;
        float c[2][8][4] = {};
        #pragma unroll
        for (int kt = 0; kt < 4; kt++) {
            // stage K d16-slice, split hi/lo
            {
                float4 kv0 = *(const float4*)(kbase + (size_t)(k0 + rowL)*D_ + kt*16 + khL);
                float4 kv1 = *(const float4*)(kbase + (size_t)(k0 + rowL)*D_ + kt*16 + khL + 4);
                float4 hh, ll;
                split4(kv0, hh, ll);
                *(float4*)&Kh[rowL*20 + khL] = hh; *(float4*)&Kl[rowL*20 + khL] = ll;
                split4(kv1, hh, ll);
                *(float4*)&Kh[rowL*20 + khL + 4] = hh; *(float4*)&Kl[rowL*20 + khL + 4] = ll;
            }
            __syncthreads();
            #pragma unroll
            for (int k8 = 0; k8 < 2; k8++) {
                const uint32_t koQ = (uint32_t)((kt*16 + k8*8) * 4);
                const uint32_t koK = (uint32_t)(k8 * 32);
                uint32_t ah[2][4], al[2][4];
                ldsm4(ah[0], aQh[0] + koQ);
                ldsm4(ah[1], aQh[1] + koQ);
                ldsm4(al[0], aQl[0] + koQ);
                ldsm4(al[1], aQl[1] + koQ);
                #pragma unroll
                for (int nj = 0; nj < 8; nj++) {
                    uint32_t bh[2], bl[2];
                    ldsm2(bh, aKh + (uint32_t)(nj*8*20*4) + koK);
                    ldsm2(bl, aKl + (uint32_t)(nj*8*20*4) + koK);
                    #pragma unroll
                    for (int mi = 0; mi < 2; mi++) {
                        mma8(c[mi][nj], ah[mi], bh);
                        mma8(c[mi][nj], ah[mi], bl);
                        mma8(c[mi][nj], al[mi], bh);
                    }
                }
            }
            __syncthreads();
        }
        // ---- epilogue: bias + scale + rowmax + raw-S store ----
        #pragma unroll
        for (int mi = 0; mi < 2; mi++) {
            #pragma unroll
            for (int half = 0; half < 2; half++) {
                const int m  = 32*wy + 16*mi + 8*half + gid;
                const int qg = qq0 + m;
                const float* brow = &sh_bias[m*7];
                float mx = pm[mi][half];
                #pragma unroll
                for (int nj = 0; nj < 8; nj++) {
                    const int kg = k0 + 64*wx + 8*nj + 2*tig;
                    int d0 = kg - qg, d1 = d0 + 1;
                    int r0 = d0 < -3 ? 0 : (d0 > 3 ? 6 : d0 + 3);
                    int r1 = d1 < -3 ? 0 : (d1 > 3 ? 6 : d1 + 3);
                    float s0 = 8.f * (c[mi][nj][2*half]     + brow[r0]);
                    float s1 = 8.f * (c[mi][nj][2*half + 1] + brow[r1]);
                    mx = fmaxf(mx, fmaxf(s0, s1));
                    *(float2*)&attn_base[(size_t)m*L_ + kg] = make_float2(s0, s1);
                }
                pm[mi][half] = mx;
            }
        }
    }

    // ---- rowmax reduce: tig lanes, then wx warps ----
    #pragma unroll
    for (int mi = 0; mi < 2; mi++)
        #pragma unroll
        for (int half = 0; half < 2; half++) {
            float v = pm[mi][half];
            v = fmaxf(v, __shfl_xor_sync(0xffffffffu, v, 1));
            v = fmaxf(v, __shfl_xor_sync(0xffffffffu, v, 2));
            if (tig == 0)
                sh_red[(32*wy + 16*mi + 8*half + gid)*2 + wx] = v;
        }
    __syncthreads();
    if (tid < TQ_) sh_rowmax[tid] = fmaxf(sh_red[tid*2], sh_red[tid*2 + 1]);
    __syncthreads();

    // ================= pass 2: exp + sums + PV via mma ====================
    const int m2   = lrow;
    const int c0   = lk4;
    const int qg2  = qq0 + m2;
    const float rm2 = sh_rowmax[m2];

    // PV warp layout: 4 wy (m: 32 rows) x 2 wx (d: 32 cols)
    uint32_t aE[2];
    {
        int r  = 32*wy + (lane & 7) + 8*((lane >> 3) & 1);
        int kcc = 4 * (lane >> 4);
        aE[0] = smem_u32(&Es[r*132 + kcc]);
        aE[1] = aE[0] + 16*132*4;
    }
    const int dbase = 32*wx;      // warp's d block (within 64)
    const int kvrow = tid >> 2, dv0 = (tid & 3) * 16;   // V loader indices

    float tsum = 0.f, s0sum = 0.f, s6sum = 0.f;
    float c2[2][4][4] = {};       // [mi][nj d8][frag]

    for (int kc = 0; kc < NCH_; kc++) {
        const int k0 = kc * TK_;
        // ---- stage V half0 (k0..k0+63), tf32-rounded ----
        #pragma unroll
        for (int t = 0; t < 4; t++) {
            float4 v = *(const float4*)(vbase + (size_t)(k0 + kvrow)*D_ + dv0 + 4*t);
            v.x = tf32_rna(v.x); v.y = tf32_rna(v.y);
            v.z = tf32_rna(v.z); v.w = tf32_rna(v.w);
            *(float4*)&Vs[kvrow*68 + dv0 + 4*t] = v;
        }
        // ---- exp stage: full-precision sums, tf32-rounded E to smem ----
        #pragma unroll
        for (int r = 0; r < 16; r++) {
            int c = c0 + 8*r;
            float4 sv = *(const float4*)(attn_base + (size_t)m2*L_ + k0 + c);
            float e0 = __expf(sv.x - rm2);
            float e1 = __expf(sv.y - rm2);
            float e2 = __expf(sv.z - rm2);
            float e3 = __expf(sv.w - rm2);
            tsum += e0 + e1 + e2 + e3;
            #pragma unroll
            for (int j = 0; j < 4; j++) {
                float e = (j == 0) ? e0 : (j == 1) ? e1 : (j == 2) ? e2 : e3;
                int dlt = k0 + c + j - qg2;
                if (dlt <= -3)      s0sum += e;
                else if (dlt >= 3)  s6sum += e;
                else                sh_pmid[m2*5 + dlt + 2] = e;
            }
            float4 er = make_float4(tf32_rna(e0), tf32_rna(e1), tf32_rna(e2), tf32_rna(e3));
            *(float4*)&Es[m2*132 + c] = er;
        }
        __syncthreads();

        // ---- PV mma half0 (k8 = 0..7) ----
        #pragma unroll
        for (int k8 = 0; k8 < 8; k8++) {
            const uint32_t ko = (uint32_t)(k8 * 32);
            uint32_t a[2][4];
            ldsm4(a[0], aE[0] + ko);
            ldsm4(a[1], aE[1] + ko);
            #pragma unroll
            for (int nj = 0; nj < 4; nj++) {
                uint32_t bb[2];
                bb[0] = __float_as_uint(Vs[(k8*8 + tig    )*68 + dbase + 8*nj + gid]);
                bb[1] = __float_as_uint(Vs[(k8*8 + tig + 4)*68 + dbase + 8*nj + gid]);
                mma8(c2[0][nj], a[0], bb);
                mma8(c2[1][nj], a[1], bb);
            }
        }
        __syncthreads();
        // ---- stage V half1 (k0+64..k0+127) ----
        #pragma unroll
        for (int t = 0; t < 4; t++) {
            float4 v = *(const float4*)(vbase + (size_t)(k0 + 64 + kvrow)*D_ + dv0 + 4*t);
            v.x = tf32_rna(v.x); v.y = tf32_rna(v.y);
            v.z = tf32_rna(v.z); v.w = tf32_rna(v.w);
            *(float4*)&Vs[kvrow*68 + dv0 + 4*t] = v;
        }
        __syncthreads();
        // ---- PV mma half1 (k8 = 8..15 of Es, rows 0..63 of Vs) ----
        #pragma unroll
        for (int k8 = 0; k8 < 8; k8++) {
            const uint32_t ko = (uint32_t)((64 + k8*8) * 4);
            uint32_t a[2][4];
            ldsm4(a[0], aE[0] + ko);
            ldsm4(a[1], aE[1] + ko);
            #pragma unroll
            for (int nj = 0; nj < 4; nj++) {
                uint32_t bb[2];
                bb[0] = __float_as_uint(Vs[(k8*8 + tig    )*68 + dbase + 8*nj + gid]);
                bb[1] = __float_as_uint(Vs[(k8*8 + tig + 4)*68 + dbase + 8*nj + gid]);
                mma8(c2[0][nj], a[0], bb);
                mma8(c2[1][nj], a[1], bb);
            }
        }
        __syncthreads();
    }

    // ---- row-sum pair reduce (two threads per row) ----
    tsum  += __shfl_xor_sync(0xffffffffu, tsum,  1);
    s0sum += __shfl_xor_sync(0xffffffffu, s0sum, 1);
    s6sum += __shfl_xor_sync(0xffffffffu, s6sum, 1);
    if ((tid & 1) == 0) { sh_T[m2] = tsum; sh_S0[m2] = s0sum; sh_S6[m2] = s6sum; }
    __syncthreads();

    // ---- w = (PV + w2) * invT from fragments -> gw [B,L,H,hd] ----
    {
        float* wbase = gw + ((size_t)(b*L_ + qq0))*D_ + h*HD_;
        #pragma unroll
        for (int mi = 0; mi < 2; mi++) {
            #pragma unroll
            for (int half = 0; half < 2; half++) {
                const int m = 32*wy + 16*mi + 8*half + gid;
                float T  = sh_T[m];
                float S0 = sh_S0[m];
                float S6 = sh_S6[m];
                float inv = 1.f / T;
                float mids[5];
                #pragma unroll
                for (int rr = 0; rr < 5; rr++) mids[rr] = sh_pmid[m*5 + rr];
                #pragma unroll
                for (int nj = 0; nj < 4; nj++) {
                    const int d0c = 32*wx + 8*nj + 2*tig;
                    float w2a = S0 * sh_relv[d0c]     + S6 * sh_relv[6*HD_ + d0c];
                    float w2b = S0 * sh_relv[d0c + 1] + S6 * sh_relv[6*HD_ + d0c + 1];
                    #pragma unroll
                    for (int rr = 0; rr < 5; rr++) {
                        w2a = fmaf(mids[rr], sh_relv[(rr+1)*HD_ + d0c],     w2a);
                        w2b = fmaf(mids[rr], sh_relv[(rr+1)*HD_ + d0c + 1], w2b);
                    }
                    float2 o;
                    o.x = (c2[mi][nj][2*half]     + w2a) * inv;
                    o.y = (c2[mi][nj][2*half + 1] + w2b) * inv;
                    *(float2*)(wbase + (size_t)m*D_ + d0c) = o;
                }
            }
        }
    }

    // ================= pass 3: normalized attn out =================
    const float inv3 = 1.f / sh_T[m2];
    #pragma unroll 4
    for (int r = 0; r < 128; r++) {
        int c = c0 + 8*r;
        float* p = attn_base + (size_t)m2*L_ + c;
        float4 a = *(const float4*)p;
        a.x = __expf(a.x - rm2) * inv3;
        a.y = __expf(a.y - rm2) * inv3;
        a.z = __expf(a.z - rm2) * inv3;
        a.w = __expf(a.w - rm2) * inv3;
        *(float4*)p = a;
    }
}

// ---------------- launch ----------------
extern "C" void kernel_launch(void* const* d_in, const int* in_sizes, int n_in,
                              void* d_out, int out_size)
{
    const float* query  = (const float*)d_in[0];
    const float* key    = (const float*)d_in[1];
    const float* value  = (const float*)d_in[2];
    const float* Wq     = (const float*)d_in[3];
    const float* Wk     = (const float*)d_in[4];
    const float* Wv     = (const float*)d_in[5];
    const float* Wproj  = (const float*)d_in[6];
    const float* b_proj = (const float*)d_in[7];
    const float* relk   = (const float*)d_in[8];
    const float* relv   = (const float*)d_in[9];

    float* out  = (float*)d_out;
    float* attn = out + (size_t)B_ * L_ * D_;   // x first, then attn

    float *gq, *gk, *gv, *gw;
    cudaGetSymbolAddress((void**)&gq, g_q);
    cudaGetSymbolAddress((void**)&gk, g_k);
    cudaGetSymbolAddress((void**)&gv, g_v);
    cudaGetSymbolAddress((void**)&gw, g_w);

    cudaFuncSetAttribute(attn_kernel, cudaFuncAttributeMaxDynamicSharedMemorySize,
                         DYN_SMEM_BYTES);

    mma_qkv_kernel<<<dim3(18, 32), 256>>>(query, key, value, Wq, Wk, Wv, gq, gk, gv);

    attn_kernel<<<dim3(L_/TQ_, H_, B_), 256, DYN_SMEM_BYTES>>>(
        gq, gk, gv, relk, relv, attn, gw);

    mma_proj_kernel<<<dim3(6, 32), 256>>>(gw, Wproj, b_proj, out);
}